// round 1
// baseline (speedup 1.0000x reference)
#include <cuda_runtime.h>
#include <cuda_bf16.h>

// Problem constants (fixed shapes from reference)
#define BB   2
#define LL   1024
#define DD   1024
#define HH   16
#define HD   64      // head dim
#define NC   16      // number of chunks per sequence
#define CH   64      // chunk length
#define MTOT (BB*LL) // 2048 rows

// Scratch (no allocations allowed in kernel_launch)
__device__ float g_Q[MTOT * DD];                 // 8 MB : normalized Q
__device__ float g_V[MTOT * DD];                 // 8 MB : normalized V
__device__ float g_S[BB * HH * NC * HD * HD];    // 8 MB : per-chunk KV sums -> exclusive prefix

// ---------------------------------------------------------------------------
// Kernel A: fused dual GEMM (X @ W^T) + per-head RMSNorm.
// Grid: (16 m-blocks of 128 rows, 16 heads (=64-col N tiles), 2 {Q,V})
// Tile: BM=128, BN=64, BK=16; 256 threads, 8x4 micro-tile per thread.
// ---------------------------------------------------------------------------
__global__ __launch_bounds__(256) void k_gemm_norm(
    const float* __restrict__ X, const float* __restrict__ Wq,
    const float* __restrict__ Wv, const float* __restrict__ qw,
    const float* __restrict__ vw)
{
    __shared__ float As[16][128];   // [k][row]
    __shared__ float Bs[16][64];    // [k][col]

    const int mblk  = blockIdx.x;
    const int h     = blockIdx.y;
    const int which = blockIdx.z;

    const float* W  = which ? Wv : Wq;
    const float* nw = (which ? vw : qw) + h * HD;
    float* Out      = which ? g_V : g_Q;

    const int tid = threadIdx.x;
    const int ty  = tid >> 4;        // 0..15
    const int tx  = tid & 15;        // 0..15
    const int r0  = ty * 8;          // 8 rows per thread
    const int c0  = tx * 4;          // 4 cols per thread

    // global->smem load mapping
    const int arow  = tid >> 1;          // 128 rows, 2 threads/row
    const int akoff = (tid & 1) * 8;     // 2 float4 per thread
    const int brow  = tid >> 2;          // 64 rows, 4 threads/row
    const int bkoff = (tid & 3) * 4;     // 1 float4 per thread

    const float* Xp = X + (size_t)(mblk * 128 + arow) * DD;
    const float* Wp = W + (size_t)(h * HD + brow) * DD;

    float acc[8][4];
#pragma unroll
    for (int i = 0; i < 8; i++)
#pragma unroll
        for (int j = 0; j < 4; j++) acc[i][j] = 0.f;

#pragma unroll 1
    for (int k0 = 0; k0 < DD; k0 += 16) {
        float4 a0 = *(const float4*)(Xp + k0 + akoff);
        float4 a1 = *(const float4*)(Xp + k0 + akoff + 4);
        float4 b0 = *(const float4*)(Wp + k0 + bkoff);
        __syncthreads();
        As[akoff + 0][arow] = a0.x;  As[akoff + 1][arow] = a0.y;
        As[akoff + 2][arow] = a0.z;  As[akoff + 3][arow] = a0.w;
        As[akoff + 4][arow] = a1.x;  As[akoff + 5][arow] = a1.y;
        As[akoff + 6][arow] = a1.z;  As[akoff + 7][arow] = a1.w;
        Bs[bkoff + 0][brow] = b0.x;  Bs[bkoff + 1][brow] = b0.y;
        Bs[bkoff + 2][brow] = b0.z;  Bs[bkoff + 3][brow] = b0.w;
        __syncthreads();
#pragma unroll
        for (int kk = 0; kk < 16; kk++) {
            float a[8], b[4];
            *(float4*)&a[0] = *(const float4*)&As[kk][r0];
            *(float4*)&a[4] = *(const float4*)&As[kk][r0 + 4];
            *(float4*)&b[0] = *(const float4*)&Bs[kk][c0];
#pragma unroll
            for (int i = 0; i < 8; i++)
#pragma unroll
                for (int j = 0; j < 4; j++)
                    acc[i][j] = fmaf(a[i], b[j], acc[i][j]);
        }
    }

    // Per-row RMS over the 64 columns of this head (inclusive of this block's
    // full BN=64 tile). Reduce partial sum-of-squares across the 16 tx lanes
    // that share the same ty (they are contiguous lanes within a warp).
#pragma unroll
    for (int i = 0; i < 8; i++) {
        float p = acc[i][0]*acc[i][0] + acc[i][1]*acc[i][1]
                + acc[i][2]*acc[i][2] + acc[i][3]*acc[i][3];
#pragma unroll
        for (int off = 1; off < 16; off <<= 1)
            p += __shfl_xor_sync(0xffffffffu, p, off, 16);
        const float inv = rsqrtf(p * (1.0f / 64.0f) + 1e-8f);
        float4 o;
        o.x = acc[i][0] * inv * nw[c0 + 0];
        o.y = acc[i][1] * inv * nw[c0 + 1];
        o.z = acc[i][2] * inv * nw[c0 + 2];
        o.w = acc[i][3] * inv * nw[c0 + 3];
        *(float4*)&Out[(size_t)(mblk * 128 + r0 + i) * DD + h * HD + c0] = o;
    }
}

// ---------------------------------------------------------------------------
// Kernel B: per-chunk KV outer-product sums. S_c[d][e] = sum_t K[t][d]*V[t][e]
// Grid: (chunk, head, batch) = (16,16,2); 256 threads, 4x4 micro-tile.
// K is raw X reshaped; V is normalized g_V.
// ---------------------------------------------------------------------------
__global__ __launch_bounds__(256) void k_chunk_kv(const float* __restrict__ X)
{
    __shared__ float Ks[64][64];
    __shared__ float Vs[64][64];

    const int c = blockIdx.x, h = blockIdx.y, b = blockIdx.z;
    const int tid = threadIdx.x;

    const int trow = tid >> 2;
    const int toff = (tid & 3) * 16;
    const float* Kg = X   + (size_t)(b * LL + c * CH + trow) * DD + h * HD;
    const float* Vg = g_V + (size_t)(b * LL + c * CH + trow) * DD + h * HD;
#pragma unroll
    for (int q = 0; q < 4; q++) {
        *(float4*)&Ks[trow][toff + 4 * q] = *(const float4*)(Kg + toff + 4 * q);
        *(float4*)&Vs[trow][toff + 4 * q] = *(const float4*)(Vg + toff + 4 * q);
    }
    __syncthreads();

    const int ty = tid >> 4, tx = tid & 15;
    const int d0 = ty * 4, e0 = tx * 4;

    float acc[4][4];
#pragma unroll
    for (int i = 0; i < 4; i++)
#pragma unroll
        for (int j = 0; j < 4; j++) acc[i][j] = 0.f;

#pragma unroll 4
    for (int t = 0; t < 64; t++) {
        float4 a  = *(const float4*)&Ks[t][d0];
        float4 b4 = *(const float4*)&Vs[t][e0];
        const float av[4] = {a.x, a.y, a.z, a.w};
        const float bv[4] = {b4.x, b4.y, b4.z, b4.w};
#pragma unroll
        for (int i = 0; i < 4; i++)
#pragma unroll
            for (int j = 0; j < 4; j++)
                acc[i][j] = fmaf(av[i], bv[j], acc[i][j]);
    }

    float* Sp = g_S + (size_t)((b * HH + h) * NC + c) * (HD * HD);
#pragma unroll
    for (int i = 0; i < 4; i++) {
        float4 o = {acc[i][0], acc[i][1], acc[i][2], acc[i][3]};
        *(float4*)&Sp[(d0 + i) * HD + e0] = o;
    }
}

// ---------------------------------------------------------------------------
// Kernel C: in-place EXCLUSIVE prefix sum of chunk states over the 16 chunks.
// Grid: 32 blocks (b*H), 256 threads; each thread owns 16 (d,e) entries.
// ---------------------------------------------------------------------------
__global__ __launch_bounds__(256) void k_prefix()
{
    const int bh = blockIdx.x;
    float* base = g_S + (size_t)bh * NC * HD * HD;
    const int tid = threadIdx.x;
#pragma unroll
    for (int j = 0; j < 16; j++) {
        const int e = tid + j * 256;
        float run = 0.f;
#pragma unroll
        for (int c = 0; c < NC; c++) {
            const float v = base[c * (HD * HD) + e];
            base[c * (HD * HD) + e] = run;
            run += v;
        }
    }
}

// ---------------------------------------------------------------------------
// Kernel D: per-chunk output.
//   O = Q @ S_prefix + causal_incl(Q @ K^T) @ V
// Grid: (chunk, head, batch); 256 threads, 4x4 micro-tile; 48KB smem.
// BufA: Q transposed [k][l], later reused for A (scores) natural [l][t].
// BufB: S natural [k][e], later V natural [t][e].
// BufC: K transposed [k][t].
// ---------------------------------------------------------------------------
__global__ __launch_bounds__(256) void k_out(const float* __restrict__ X,
                                             float* __restrict__ Out)
{
    __shared__ float BufA[64][64];
    __shared__ float BufB[64][64];
    __shared__ float BufC[64][64];

    const int c = blockIdx.x, h = blockIdx.y, b = blockIdx.z;
    const int tid = threadIdx.x;

    // Load Q (transposed) and K (transposed)
    {
        const int lrow = tid >> 2;
        const int koff = (tid & 3) * 16;
        const float* Qg = g_Q + (size_t)(b * LL + c * CH + lrow) * DD + h * HD;
        const float* Kg = X   + (size_t)(b * LL + c * CH + lrow) * DD + h * HD;
#pragma unroll
        for (int q = 0; q < 4; q++) {
            float4 v = *(const float4*)(Qg + koff + 4 * q);
            BufA[koff + 4*q + 0][lrow] = v.x; BufA[koff + 4*q + 1][lrow] = v.y;
            BufA[koff + 4*q + 2][lrow] = v.z; BufA[koff + 4*q + 3][lrow] = v.w;
            float4 w = *(const float4*)(Kg + koff + 4 * q);
            BufC[koff + 4*q + 0][lrow] = w.x; BufC[koff + 4*q + 1][lrow] = w.y;
            BufC[koff + 4*q + 2][lrow] = w.z; BufC[koff + 4*q + 3][lrow] = w.w;
        }
        // Load S_prefix (natural layout, straight float4 copy)
        const float* Sp = g_S + (size_t)((b * HH + h) * NC + c) * (HD * HD);
#pragma unroll
        for (int j = 0; j < 4; j++) {
            const int idx = tid + j * 256;
            ((float4*)&BufB[0][0])[idx] = ((const float4*)Sp)[idx];
        }
    }
    __syncthreads();

    const int ty = tid >> 4, tx = tid & 15;
    const int l0 = ty * 4;          // token rows
    const int e0 = tx * 4;          // out cols (stage1/3) / score cols t (stage2)

    float O[4][4];
#pragma unroll
    for (int i = 0; i < 4; i++)
#pragma unroll
        for (int j = 0; j < 4; j++) O[i][j] = 0.f;

    // Stage 1: O = Q @ S_prefix
#pragma unroll 4
    for (int k = 0; k < 64; k++) {
        float4 a  = *(const float4*)&BufA[k][l0];
        float4 b4 = *(const float4*)&BufB[k][e0];
        const float av[4] = {a.x, a.y, a.z, a.w};
        const float bv[4] = {b4.x, b4.y, b4.z, b4.w};
#pragma unroll
        for (int i = 0; i < 4; i++)
#pragma unroll
            for (int j = 0; j < 4; j++)
                O[i][j] = fmaf(av[i], bv[j], O[i][j]);
    }

    // Stage 2: A = causal_incl(Q @ K^T)
    float A[4][4];
#pragma unroll
    for (int i = 0; i < 4; i++)
#pragma unroll
        for (int j = 0; j < 4; j++) A[i][j] = 0.f;

#pragma unroll 4
    for (int k = 0; k < 64; k++) {
        float4 a  = *(const float4*)&BufA[k][l0];
        float4 b4 = *(const float4*)&BufC[k][e0];
        const float av[4] = {a.x, a.y, a.z, a.w};
        const float bv[4] = {b4.x, b4.y, b4.z, b4.w};
#pragma unroll
        for (int i = 0; i < 4; i++)
#pragma unroll
            for (int j = 0; j < 4; j++)
                A[i][j] = fmaf(av[i], bv[j], A[i][j]);
    }
#pragma unroll
    for (int i = 0; i < 4; i++)
#pragma unroll
        for (int j = 0; j < 4; j++)
            if (e0 + j > l0 + i) A[i][j] = 0.f;  // keep t <= l (inclusive cumsum)

    __syncthreads();   // everyone done reading BufA(Q) and BufB(S)

    // Store A into BufA natural [l][t]; load V into BufB natural [t][e]
#pragma unroll
    for (int i = 0; i < 4; i++)
#pragma unroll
        for (int j = 0; j < 4; j++)
            BufA[l0 + i][e0 + j] = A[i][j];
    {
        const int trow = tid >> 2;
        const int eoff = (tid & 3) * 16;
        const float* Vg = g_V + (size_t)(b * LL + c * CH + trow) * DD + h * HD;
#pragma unroll
        for (int q = 0; q < 4; q++)
            *(float4*)&BufB[trow][eoff + 4 * q] = *(const float4*)(Vg + eoff + 4 * q);
    }
    __syncthreads();

    // Stage 3: O += A @ V   (A read as scalars: broadcast across tx lanes)
#pragma unroll 4
    for (int t = 0; t < 64; t++) {
        const float av[4] = {BufA[l0 + 0][t], BufA[l0 + 1][t],
                             BufA[l0 + 2][t], BufA[l0 + 3][t]};
        float4 b4 = *(const float4*)&BufB[t][e0];
        const float bv[4] = {b4.x, b4.y, b4.z, b4.w};
#pragma unroll
        for (int i = 0; i < 4; i++)
#pragma unroll
            for (int j = 0; j < 4; j++)
                O[i][j] = fmaf(av[i], bv[j], O[i][j]);
    }

    // Write output (B, L, D) row-major
    float* Op = Out + (size_t)(b * LL + c * CH) * DD + h * HD;
#pragma unroll
    for (int i = 0; i < 4; i++) {
        float4 o = {O[i][0], O[i][1], O[i][2], O[i][3]};
        *(float4*)&Op[(size_t)(l0 + i) * DD + e0] = o;
    }
}

// ---------------------------------------------------------------------------
extern "C" void kernel_launch(void* const* d_in, const int* in_sizes, int n_in,
                              void* d_out, int out_size)
{
    const float* X  = (const float*)d_in[0];
    const float* Wq = (const float*)d_in[1];
    const float* Wv = (const float*)d_in[2];
    const float* qw = (const float*)d_in[3];
    const float* vw = (const float*)d_in[4];
    float* Out = (float*)d_out;

    k_gemm_norm<<<dim3(16, 16, 2), 256>>>(X, Wq, Wv, qw, vw);
    k_chunk_kv <<<dim3(16, 16, 2), 256>>>(X);
    k_prefix   <<<BB * HH, 256>>>();
    k_out      <<<dim3(16, 16, 2), 256>>>(X, Out);
}

// round 4
// speedup vs baseline: 1.9553x; 1.9553x over previous
#include <cuda_runtime.h>
#include <cuda_bf16.h>
#include <cstdint>

// Problem constants (fixed shapes from reference)
#define BB   2
#define LL   1024
#define DD   1024
#define HH   16
#define HD   64      // head dim
#define NC   16      // number of chunks per sequence
#define CH   64      // chunk length
#define MTOT (BB*LL) // 2048 rows

// Projection GEMM: bf16x3 split, K' = 3*D
// A' = [Ahi | Alo | Ahi],  B' = [Bhi | Bhi | Blo]
//  =>  A'.B' = Ahi.Bhi + Alo.Bhi + Ahi.Blo   (drops only Alo.Blo ~ 2^-18)
#define KT2  3072
#define BK   64
#define GITER (KT2/BK)    // 48
#define BM   128
#define BN   128
#define ROWB 144          // padded smem row stride in bytes (64 bf16 + 8 pad)
#define ASZ  (128*ROWB)   // 18432 bytes per tile buffer

// Scratch (no allocations allowed in kernel_launch)
__device__ float g_Q[MTOT * DD];                 // 8 MB : normalized Q
__device__ float g_V[MTOT * DD];                 // 8 MB : normalized V
__device__ float g_S[BB * HH * NC * HD * HD];    // 8 MB : per-chunk KV sums
__device__ __nv_bfloat16 g_Ax [MTOT * KT2];      // 12 MB : [Xhi | Xlo | Xhi]
__device__ __nv_bfloat16 g_Wq2[DD * KT2];        // 6 MB  : [Whi | Whi | Wlo]
__device__ __nv_bfloat16 g_Wv2[DD * KT2];        // 6 MB

static __device__ __forceinline__ uint32_t s2u(const void* p) {
    uint32_t a;
    asm("{ .reg .u64 t; cvta.to.shared.u64 t, %1; cvt.u32.u64 %0, t; }"
        : "=r"(a) : "l"(p));
    return a;
}

#define CP_ASYNC16(saddr, gptr) \
    asm volatile("cp.async.cg.shared.global [%0], [%1], 16;" \
                 :: "r"(saddr), "l"(gptr))
#define CP_COMMIT() asm volatile("cp.async.commit_group;")
#define CP_WAIT(n)  asm volatile("cp.async.wait_group %0;" :: "n"(n))

#define LDMATRIX_X4(r0, r1, r2, r3, addr) \
    asm volatile("ldmatrix.sync.aligned.m8n8.x4.shared.b16 {%0,%1,%2,%3}, [%4];" \
                 : "=r"(r0), "=r"(r1), "=r"(r2), "=r"(r3) : "r"(addr))

#define MMA16816(d, a, b) \
    asm volatile("mma.sync.aligned.m16n8k16.row.col.f32.bf16.bf16.f32 " \
                 "{%0,%1,%2,%3}, {%4,%5,%6,%7}, {%8,%9}, {%0,%1,%2,%3};" \
                 : "+f"((d)[0]), "+f"((d)[1]), "+f"((d)[2]), "+f"((d)[3]) \
                 : "r"((a)[0]), "r"((a)[1]), "r"((a)[2]), "r"((a)[3]),   \
                   "r"((b)[0]), "r"((b)[1]))

// ---------------------------------------------------------------------------
// Kernel S: fp32 -> bf16x3 split along K.
// z=0: X -> g_Ax as [hi | lo | hi]
// z=1: Wq -> g_Wq2 as [hi | hi | lo];  z=2: Wv -> g_Wv2 likewise.
// ---------------------------------------------------------------------------
__global__ __launch_bounds__(256) void k_split(
    const float* __restrict__ X, const float* __restrict__ Wq,
    const float* __restrict__ Wv)
{
    const int z = blockIdx.z;
    const float* src = (z == 0) ? X : (z == 1) ? Wq : Wv;
    __nv_bfloat16* dst = (z == 0) ? g_Ax : (z == 1) ? g_Wq2 : g_Wv2;
    const int rows = (z == 0) ? MTOT : DD;

    const int gid = blockIdx.x * 256 + threadIdx.x;
    if (gid * 4 >= rows * DD) return;
    const int row = (gid * 4) >> 10;
    const int col = (gid * 4) & 1023;

    float4 v = *(const float4*)(src + (size_t)row * DD + col);
    float vs[4] = {v.x, v.y, v.z, v.w};
    __nv_bfloat16 h[4], l[4];
#pragma unroll
    for (int i = 0; i < 4; i++) {
        h[i] = __float2bfloat16(vs[i]);
        l[i] = __float2bfloat16(vs[i] - __bfloat162float(h[i]));
    }
    __nv_bfloat162 hp0 = __halves2bfloat162(h[0], h[1]);
    __nv_bfloat162 hp1 = __halves2bfloat162(h[2], h[3]);
    __nv_bfloat162 lp0 = __halves2bfloat162(l[0], l[1]);
    __nv_bfloat162 lp1 = __halves2bfloat162(l[2], l[3]);

    __nv_bfloat16* base = dst + (size_t)row * KT2 + col;
    // segment 0: hi (both A and B)
    ((__nv_bfloat162*)(base))[0] = hp0;
    ((__nv_bfloat162*)(base))[1] = hp1;
    if (z == 0) {
        // A: segment 1 = lo, segment 2 = hi
        ((__nv_bfloat162*)(base + DD))[0] = lp0;
        ((__nv_bfloat162*)(base + DD))[1] = lp1;
        ((__nv_bfloat162*)(base + 2 * DD))[0] = hp0;
        ((__nv_bfloat162*)(base + 2 * DD))[1] = hp1;
    } else {
        // B: segment 1 = hi, segment 2 = lo
        ((__nv_bfloat162*)(base + DD))[0] = hp0;
        ((__nv_bfloat162*)(base + DD))[1] = hp1;
        ((__nv_bfloat162*)(base + 2 * DD))[0] = lp0;
        ((__nv_bfloat162*)(base + 2 * DD))[1] = lp1;
    }
}

// ---------------------------------------------------------------------------
// Kernel P: projection GEMM via mma.sync (HMMA) + fused per-head RMSNorm.
// C[m][n] = sum_k' A'[m][k'] * B'[n][k'];  Grid (16 m-tiles, 8 n-tiles, 2).
// 256 threads = 8 warps; warp tile 32(m) x 64(n); BK=64 double-buffered
// via cp.async; smem rows padded to 144B (conflict-free ldmatrix).
// ---------------------------------------------------------------------------
__global__ __launch_bounds__(256, 2) void k_proj(
    const float* __restrict__ qw, const float* __restrict__ vw)
{
    extern __shared__ char smem[];
    const int tid = threadIdx.x, wid = tid >> 5, lane = tid & 31;
    const int mblk = blockIdx.x, nblk = blockIdx.y, z = blockIdx.z;

    const uint32_t sA[2] = { s2u(smem),            s2u(smem) + ASZ };
    const uint32_t sB[2] = { s2u(smem) + 2 * ASZ,  s2u(smem) + 3 * ASZ };

    const __nv_bfloat16* Ag = g_Ax + (size_t)mblk * BM * KT2;
    const __nv_bfloat16* Bg = (z ? g_Wv2 : g_Wq2) + (size_t)nblk * BN * KT2;

    // Per-thread cp.async mapping: 1024 16B-chunks per tile, 4 per thread.
    const int ldrow = tid >> 3;          // base row, step 32
    const int ldch  = tid & 7;

    auto load_tile = [&](int buf, int k0) {
#pragma unroll
        for (int j = 0; j < 4; j++) {
            const int row = ldrow + j * 32;
            CP_ASYNC16(sA[buf] + row * ROWB + ldch * 16,
                       Ag + (size_t)row * KT2 + k0 + ldch * 8);
        }
#pragma unroll
        for (int j = 0; j < 4; j++) {
            const int row = ldrow + j * 32;
            CP_ASYNC16(sB[buf] + row * ROWB + ldch * 16,
                       Bg + (size_t)row * KT2 + k0 + ldch * 8);
        }
        CP_COMMIT();
    };

    float acc[2][8][4];
#pragma unroll
    for (int i = 0; i < 2; i++)
#pragma unroll
        for (int j = 0; j < 8; j++)
#pragma unroll
            for (int q = 0; q < 4; q++) acc[i][j][q] = 0.f;

    const int mbase = (wid >> 1) * 32;      // warp m-offset within 128
    const int nbase = (wid & 1) * 64;       // warp n-offset within 128

    // ldmatrix source addresses (fixed row parts)
    const int a_row = (lane & 15);
    const int a_off = (lane >> 4) * 16;
    const int b_row = ((lane >> 4) << 3) + (lane & 7);
    const int b_off = ((lane >> 3) & 1) * 16;

    load_tile(0, 0);

#pragma unroll 1
    for (int it = 0; it < GITER; it++) {
        const int buf = it & 1;
        if (it + 1 < GITER) load_tile(buf ^ 1, (it + 1) * BK);
        if (it + 1 < GITER) { CP_WAIT(1); } else { CP_WAIT(0); }
        __syncthreads();

#pragma unroll
        for (int k16 = 0; k16 < 4; k16++) {
            uint32_t a[2][4];
#pragma unroll
            for (int i = 0; i < 2; i++) {
                const uint32_t addr = sA[buf]
                    + (mbase + i * 16 + a_row) * ROWB + k16 * 32 + a_off;
                LDMATRIX_X4(a[i][0], a[i][1], a[i][2], a[i][3], addr);
            }
            uint32_t b[4][4];
#pragma unroll
            for (int g = 0; g < 4; g++) {
                const uint32_t addr = sB[buf]
                    + (nbase + g * 16 + b_row) * ROWB + k16 * 32 + b_off;
                LDMATRIX_X4(b[g][0], b[g][1], b[g][2], b[g][3], addr);
            }
#pragma unroll
            for (int i = 0; i < 2; i++)
#pragma unroll
                for (int g = 0; g < 4; g++) {
                    MMA16816(acc[i][2 * g],     a[i], (&b[g][0]));
                    MMA16816(acc[i][2 * g + 1], a[i], (&b[g][2]));
                }
        }
        __syncthreads();
    }

    // Epilogue: per-head RMSNorm; warp owns a full 64-wide head.
    const int head = nblk * 2 + (wid & 1);
    const float* nw = (z ? vw : qw) + head * HD;
    float* Out = (z ? g_V : g_Q);

    float nwv[8][2];
#pragma unroll
    for (int j = 0; j < 8; j++) {
        float2 t = *(const float2*)(nw + j * 8 + 2 * (lane & 3));
        nwv[j][0] = t.x; nwv[j][1] = t.y;
    }

#pragma unroll
    for (int i = 0; i < 2; i++) {
#pragma unroll
        for (int hh = 0; hh < 2; hh++) {   // row halves: c0/c1 vs c2/c3
            float ss = 0.f;
#pragma unroll
            for (int j = 0; j < 8; j++) {
                const float v0 = acc[i][j][2 * hh];
                const float v1 = acc[i][j][2 * hh + 1];
                ss = fmaf(v0, v0, fmaf(v1, v1, ss));
            }
            ss += __shfl_xor_sync(0xffffffffu, ss, 1);
            ss += __shfl_xor_sync(0xffffffffu, ss, 2);
            const float inv = rsqrtf(ss * (1.0f / 64.0f) + 1e-8f);

            const int row = mblk * BM + mbase + i * 16 + hh * 8 + (lane >> 2);
            float* op = Out + (size_t)row * DD + head * HD + 2 * (lane & 3);
#pragma unroll
            for (int j = 0; j < 8; j++) {
                float2 o;
                o.x = acc[i][j][2 * hh]     * inv * nwv[j][0];
                o.y = acc[i][j][2 * hh + 1] * inv * nwv[j][1];
                *(float2*)(op + j * 8) = o;
            }
        }
    }
}

// ---------------------------------------------------------------------------
// Kernel B: per-chunk KV outer-product sums. S_c[d][e] = sum_t K[t][d]*V[t][e]
// ---------------------------------------------------------------------------
__global__ __launch_bounds__(256) void k_chunk_kv(const float* __restrict__ X)
{
    __shared__ float Ks[64][64];
    __shared__ float Vs[64][64];

    const int c = blockIdx.x, h = blockIdx.y, b = blockIdx.z;
    const int tid = threadIdx.x;

    const int trow = tid >> 2;
    const int toff = (tid & 3) * 16;
    const float* Kg = X   + (size_t)(b * LL + c * CH + trow) * DD + h * HD;
    const float* Vg = g_V + (size_t)(b * LL + c * CH + trow) * DD + h * HD;
#pragma unroll
    for (int q = 0; q < 4; q++) {
        *(float4*)&Ks[trow][toff + 4 * q] = *(const float4*)(Kg + toff + 4 * q);
        *(float4*)&Vs[trow][toff + 4 * q] = *(const float4*)(Vg + toff + 4 * q);
    }
    __syncthreads();

    const int ty = tid >> 4, tx = tid & 15;
    const int d0 = ty * 4, e0 = tx * 4;

    float acc[4][4];
#pragma unroll
    for (int i = 0; i < 4; i++)
#pragma unroll
        for (int j = 0; j < 4; j++) acc[i][j] = 0.f;

#pragma unroll 4
    for (int t = 0; t < 64; t++) {
        float4 a  = *(const float4*)&Ks[t][d0];
        float4 b4 = *(const float4*)&Vs[t][e0];
        const float av[4] = {a.x, a.y, a.z, a.w};
        const float bv[4] = {b4.x, b4.y, b4.z, b4.w};
#pragma unroll
        for (int i = 0; i < 4; i++)
#pragma unroll
            for (int j = 0; j < 4; j++)
                acc[i][j] = fmaf(av[i], bv[j], acc[i][j]);
    }

    float* Sp = g_S + (size_t)((b * HH + h) * NC + c) * (HD * HD);
#pragma unroll
    for (int i = 0; i < 4; i++) {
        float4 o = {acc[i][0], acc[i][1], acc[i][2], acc[i][3]};
        *(float4*)&Sp[(d0 + i) * HD + e0] = o;
    }
}

// ---------------------------------------------------------------------------
// Kernel C: in-place EXCLUSIVE prefix sum of chunk states over the 16 chunks.
// ---------------------------------------------------------------------------
__global__ __launch_bounds__(256) void k_prefix()
{
    const int bh = blockIdx.x;
    float* base = g_S + (size_t)bh * NC * HD * HD;
    const int tid = threadIdx.x;
#pragma unroll
    for (int j = 0; j < 16; j++) {
        const int e = tid + j * 256;
        float run = 0.f;
#pragma unroll
        for (int c = 0; c < NC; c++) {
            const float v = base[c * (HD * HD) + e];
            base[c * (HD * HD) + e] = run;
            run += v;
        }
    }
}

// ---------------------------------------------------------------------------
// Kernel D: per-chunk output.  O = Q @ S_prefix + causal_incl(Q @ K^T) @ V
// ---------------------------------------------------------------------------
__global__ __launch_bounds__(256) void k_out(const float* __restrict__ X,
                                             float* __restrict__ Out)
{
    __shared__ float BufA[64][64];
    __shared__ float BufB[64][64];
    __shared__ float BufC[64][64];

    const int c = blockIdx.x, h = blockIdx.y, b = blockIdx.z;
    const int tid = threadIdx.x;

    {
        const int lrow = tid >> 2;
        const int koff = (tid & 3) * 16;
        const float* Qg = g_Q + (size_t)(b * LL + c * CH + lrow) * DD + h * HD;
        const float* Kg = X   + (size_t)(b * LL + c * CH + lrow) * DD + h * HD;
#pragma unroll
        for (int q = 0; q < 4; q++) {
            float4 v = *(const float4*)(Qg + koff + 4 * q);
            BufA[koff + 4*q + 0][lrow] = v.x; BufA[koff + 4*q + 1][lrow] = v.y;
            BufA[koff + 4*q + 2][lrow] = v.z; BufA[koff + 4*q + 3][lrow] = v.w;
            float4 w = *(const float4*)(Kg + koff + 4 * q);
            BufC[koff + 4*q + 0][lrow] = w.x; BufC[koff + 4*q + 1][lrow] = w.y;
            BufC[koff + 4*q + 2][lrow] = w.z; BufC[koff + 4*q + 3][lrow] = w.w;
        }
        const float* Sp = g_S + (size_t)((b * HH + h) * NC + c) * (HD * HD);
#pragma unroll
        for (int j = 0; j < 4; j++) {
            const int idx = tid + j * 256;
            ((float4*)&BufB[0][0])[idx] = ((const float4*)Sp)[idx];
        }
    }
    __syncthreads();

    const int ty = tid >> 4, tx = tid & 15;
    const int l0 = ty * 4;
    const int e0 = tx * 4;

    float O[4][4];
#pragma unroll
    for (int i = 0; i < 4; i++)
#pragma unroll
        for (int j = 0; j < 4; j++) O[i][j] = 0.f;

#pragma unroll 4
    for (int k = 0; k < 64; k++) {
        float4 a  = *(const float4*)&BufA[k][l0];
        float4 b4 = *(const float4*)&BufB[k][e0];
        const float av[4] = {a.x, a.y, a.z, a.w};
        const float bv[4] = {b4.x, b4.y, b4.z, b4.w};
#pragma unroll
        for (int i = 0; i < 4; i++)
#pragma unroll
            for (int j = 0; j < 4; j++)
                O[i][j] = fmaf(av[i], bv[j], O[i][j]);
    }

    float A[4][4];
#pragma unroll
    for (int i = 0; i < 4; i++)
#pragma unroll
        for (int j = 0; j < 4; j++) A[i][j] = 0.f;

#pragma unroll 4
    for (int k = 0; k < 64; k++) {
        float4 a  = *(const float4*)&BufA[k][l0];
        float4 b4 = *(const float4*)&BufC[k][e0];
        const float av[4] = {a.x, a.y, a.z, a.w};
        const float bv[4] = {b4.x, b4.y, b4.z, b4.w};
#pragma unroll
        for (int i = 0; i < 4; i++)
#pragma unroll
            for (int j = 0; j < 4; j++)
                A[i][j] = fmaf(av[i], bv[j], A[i][j]);
    }
#pragma unroll
    for (int i = 0; i < 4; i++)
#pragma unroll
        for (int j = 0; j < 4; j++)
            if (e0 + j > l0 + i) A[i][j] = 0.f;

    __syncthreads();

#pragma unroll
    for (int i = 0; i < 4; i++)
#pragma unroll
        for (int j = 0; j < 4; j++)
            BufA[l0 + i][e0 + j] = A[i][j];
    {
        const int trow = tid >> 2;
        const int eoff = (tid & 3) * 16;
        const float* Vg = g_V + (size_t)(b * LL + c * CH + trow) * DD + h * HD;
#pragma unroll
        for (int q = 0; q < 4; q++)
            *(float4*)&BufB[trow][eoff + 4 * q] = *(const float4*)(Vg + eoff + 4 * q);
    }
    __syncthreads();

#pragma unroll 4
    for (int t = 0; t < 64; t++) {
        const float av[4] = {BufA[l0 + 0][t], BufA[l0 + 1][t],
                             BufA[l0 + 2][t], BufA[l0 + 3][t]};
        float4 b4 = *(const float4*)&BufB[t][e0];
        const float bv[4] = {b4.x, b4.y, b4.z, b4.w};
#pragma unroll
        for (int i = 0; i < 4; i++)
#pragma unroll
            for (int j = 0; j < 4; j++)
                O[i][j] = fmaf(av[i], bv[j], O[i][j]);
    }

    float* Op = Out + (size_t)(b * LL + c * CH) * DD + h * HD;
#pragma unroll
    for (int i = 0; i < 4; i++) {
        float4 o = {O[i][0], O[i][1], O[i][2], O[i][3]};
        *(float4*)&Op[(size_t)(l0 + i) * DD + e0] = o;
    }
}

// ---------------------------------------------------------------------------
extern "C" void kernel_launch(void* const* d_in, const int* in_sizes, int n_in,
                              void* d_out, int out_size)
{
    const float* X  = (const float*)d_in[0];
    const float* Wq = (const float*)d_in[1];
    const float* Wv = (const float*)d_in[2];
    const float* qw = (const float*)d_in[3];
    const float* vw = (const float*)d_in[4];
    float* Out = (float*)d_out;

    const int SMEM_PROJ = 4 * ASZ;  // 73728 bytes
    cudaFuncSetAttribute(k_proj, cudaFuncAttributeMaxDynamicSharedMemorySize,
                         SMEM_PROJ);

    k_split   <<<dim3(2048, 1, 3), 256>>>(X, Wq, Wv);
    k_proj    <<<dim3(16, 8, 2), 256, SMEM_PROJ>>>(qw, vw);
    k_chunk_kv<<<dim3(16, 16, 2), 256>>>(X);
    k_prefix  <<<BB * HH, 256>>>();
    k_out     <<<dim3(16, 16, 2), 256>>>(X, Out);
}

// round 5
// speedup vs baseline: 2.1014x; 1.0747x over previous
#include <cuda_runtime.h>
#include <cuda_bf16.h>
#include <cstdint>
#include <cstring>

// Problem constants (fixed shapes from reference)
#define BB   2
#define LL   1024
#define DD   1024
#define HH   16
#define HD   64      // head dim
#define NC   16      // number of chunks per sequence
#define CH   64      // chunk length
#define MTOT (BB*LL) // 2048 rows

// Projection GEMM: bf16x3 split, K' = 3*D
// A' = [Ahi | Alo | Ahi],  B' = [Bhi | Bhi | Blo]
//  =>  A'.B' = Ahi.Bhi + Alo.Bhi + Ahi.Blo   (drops only Alo.Blo ~ 2^-18)
#define KT2  3072
#define BK   64
#define GITER (KT2/BK)    // 48
#define BM   128
#define BN   128
#define ROWB 144          // padded smem row stride in bytes (64 bf16 + 8 pad)
#define ASZ  (128*ROWB)   // 18432 bytes per tile buffer
#define NSTAGE 3

// Scratch (no allocations allowed in kernel_launch)
__device__ float g_Q[MTOT * DD];                 // 8 MB : normalized Q
__device__ float g_V[MTOT * DD];                 // 8 MB : normalized V
__device__ float g_S[BB * HH * NC * HD * HD];    // 8 MB : per-chunk KV sums
__device__ __nv_bfloat16 g_Ax [MTOT * KT2];      // 12 MB : [Xhi | Xlo | Xhi]
__device__ __nv_bfloat16 g_Wq2[DD * KT2];        // 6 MB  : [Whi | Whi | Wlo]
__device__ __nv_bfloat16 g_Wv2[DD * KT2];        // 6 MB

static __device__ __forceinline__ uint32_t s2u(const void* p) {
    uint32_t a;
    asm("{ .reg .u64 t; cvta.to.shared.u64 t, %1; cvt.u32.u64 %0, t; }"
        : "=r"(a) : "l"(p));
    return a;
}
static __device__ __forceinline__ uint32_t b2u(__nv_bfloat162 v) {
    uint32_t u; memcpy(&u, &v, 4); return u;
}

#define CP_ASYNC16(saddr, gptr) \
    asm volatile("cp.async.cg.shared.global [%0], [%1], 16;" \
                 :: "r"(saddr), "l"(gptr))
#define CP_COMMIT() asm volatile("cp.async.commit_group;")
#define CP_WAIT(n)  asm volatile("cp.async.wait_group %0;" :: "n"(n))

#define LDMATRIX_X4(r0, r1, r2, r3, addr) \
    asm volatile("ldmatrix.sync.aligned.m8n8.x4.shared.b16 {%0,%1,%2,%3}, [%4];" \
                 : "=r"(r0), "=r"(r1), "=r"(r2), "=r"(r3) : "r"(addr))

#define MMA16816(d, a, b) \
    asm volatile("mma.sync.aligned.m16n8k16.row.col.f32.bf16.bf16.f32 " \
                 "{%0,%1,%2,%3}, {%4,%5,%6,%7}, {%8,%9}, {%0,%1,%2,%3};" \
                 : "+f"((d)[0]), "+f"((d)[1]), "+f"((d)[2]), "+f"((d)[3]) \
                 : "r"((a)[0]), "r"((a)[1]), "r"((a)[2]), "r"((a)[3]),   \
                   "r"((b)[0]), "r"((b)[1]))

// ---------------------------------------------------------------------------
// Kernel S: fp32 -> bf16x3 split along K.  8 elements/thread, 16B stores.
// z=0: X -> g_Ax as [hi | lo | hi]
// z=1: Wq -> g_Wq2 as [hi | hi | lo];  z=2: Wv -> g_Wv2 likewise.
// ---------------------------------------------------------------------------
__global__ __launch_bounds__(256) void k_split(
    const float* __restrict__ X, const float* __restrict__ Wq,
    const float* __restrict__ Wv)
{
    const int z = blockIdx.z;
    const float* src = (z == 0) ? X : (z == 1) ? Wq : Wv;
    __nv_bfloat16* dst = (z == 0) ? g_Ax : (z == 1) ? g_Wq2 : g_Wv2;
    const int rows = (z == 0) ? MTOT : DD;

    const int gid = blockIdx.x * 256 + threadIdx.x;
    const int idx8 = gid * 8;
    if (idx8 >= rows * DD) return;
    const int row = idx8 >> 10;
    const int col = idx8 & 1023;

    const float* sp = src + (size_t)row * DD + col;
    float4 v0 = *(const float4*)(sp);
    float4 v1 = *(const float4*)(sp + 4);
    float vs[8] = {v0.x, v0.y, v0.z, v0.w, v1.x, v1.y, v1.z, v1.w};
    __nv_bfloat16 h[8], l[8];
#pragma unroll
    for (int i = 0; i < 8; i++) {
        h[i] = __float2bfloat16(vs[i]);
        l[i] = __float2bfloat16(vs[i] - __bfloat162float(h[i]));
    }
    uint4 HU, LU;
    HU.x = b2u(__halves2bfloat162(h[0], h[1]));
    HU.y = b2u(__halves2bfloat162(h[2], h[3]));
    HU.z = b2u(__halves2bfloat162(h[4], h[5]));
    HU.w = b2u(__halves2bfloat162(h[6], h[7]));
    LU.x = b2u(__halves2bfloat162(l[0], l[1]));
    LU.y = b2u(__halves2bfloat162(l[2], l[3]));
    LU.z = b2u(__halves2bfloat162(l[4], l[5]));
    LU.w = b2u(__halves2bfloat162(l[6], l[7]));

    __nv_bfloat16* base = dst + (size_t)row * KT2 + col;
    *(uint4*)(base) = HU;                                 // seg0 = hi
    *(uint4*)(base + DD)     = (z == 0) ? LU : HU;        // seg1
    *(uint4*)(base + 2 * DD) = (z == 0) ? HU : LU;        // seg2
}

// ---------------------------------------------------------------------------
// Kernel P: projection GEMM via mma.sync (HMMA) + fused per-head RMSNorm.
// 3-stage cp.async pipeline, one __syncthreads per iteration.
// Grid (16 m-tiles, 8 n-tiles, 2 {Q,V}); 8 warps; warp tile 32x64.
// ---------------------------------------------------------------------------
__global__ __launch_bounds__(256, 2) void k_proj(
    const float* __restrict__ qw, const float* __restrict__ vw)
{
    extern __shared__ char smem[];
    const int tid = threadIdx.x, wid = tid >> 5, lane = tid & 31;
    const int mblk = blockIdx.x, nblk = blockIdx.y, z = blockIdx.z;

    const uint32_t sA0 = s2u(smem);
    const uint32_t sB0 = sA0 + NSTAGE * ASZ;

    const __nv_bfloat16* Ag = g_Ax + (size_t)mblk * BM * KT2;
    const __nv_bfloat16* Bg = (z ? g_Wv2 : g_Wq2) + (size_t)nblk * BN * KT2;

    // Per-thread cp.async mapping: 1024 16B-chunks per tile, 4 per thread.
    const int ldrow = tid >> 3;          // base row, step 32
    const int ldch  = tid & 7;

    auto load_tile = [&](int buf, int k0) {
        const uint32_t a = sA0 + buf * ASZ;
        const uint32_t b = sB0 + buf * ASZ;
#pragma unroll
        for (int j = 0; j < 4; j++) {
            const int row = ldrow + j * 32;
            CP_ASYNC16(a + row * ROWB + ldch * 16,
                       Ag + (size_t)row * KT2 + k0 + ldch * 8);
        }
#pragma unroll
        for (int j = 0; j < 4; j++) {
            const int row = ldrow + j * 32;
            CP_ASYNC16(b + row * ROWB + ldch * 16,
                       Bg + (size_t)row * KT2 + k0 + ldch * 8);
        }
        CP_COMMIT();
    };

    float acc[2][8][4];
#pragma unroll
    for (int i = 0; i < 2; i++)
#pragma unroll
        for (int j = 0; j < 8; j++)
#pragma unroll
            for (int q = 0; q < 4; q++) acc[i][j][q] = 0.f;

    const int mbase = (wid >> 1) * 32;      // warp m-offset within 128
    const int nbase = (wid & 1) * 64;       // warp n-offset within 128

    // ldmatrix source addresses (fixed row parts)
    const int a_row = (lane & 15);
    const int a_off = (lane >> 4) * 16;
    const int b_row = ((lane >> 4) << 3) + (lane & 7);
    const int b_off = ((lane >> 3) & 1) * 16;

    load_tile(0, 0);
    load_tile(1, BK);

#pragma unroll 1
    for (int it = 0; it < GITER; it++) {
        const int buf = it % NSTAGE;
        CP_WAIT(1);              // group `it` complete
        __syncthreads();         // everyone past reads of buffer (it-1)%3
        if (it + 2 < GITER) load_tile((it + 2) % NSTAGE, (it + 2) * BK);

        const uint32_t sAb = sA0 + buf * ASZ;
        const uint32_t sBb = sB0 + buf * ASZ;
#pragma unroll
        for (int k16 = 0; k16 < 4; k16++) {
            uint32_t a[2][4];
#pragma unroll
            for (int i = 0; i < 2; i++) {
                const uint32_t addr = sAb
                    + (mbase + i * 16 + a_row) * ROWB + k16 * 32 + a_off;
                LDMATRIX_X4(a[i][0], a[i][1], a[i][2], a[i][3], addr);
            }
            uint32_t b[4][4];
#pragma unroll
            for (int g = 0; g < 4; g++) {
                const uint32_t addr = sBb
                    + (nbase + g * 16 + b_row) * ROWB + k16 * 32 + b_off;
                LDMATRIX_X4(b[g][0], b[g][1], b[g][2], b[g][3], addr);
            }
#pragma unroll
            for (int i = 0; i < 2; i++)
#pragma unroll
                for (int g = 0; g < 4; g++) {
                    MMA16816(acc[i][2 * g],     a[i], (&b[g][0]));
                    MMA16816(acc[i][2 * g + 1], a[i], (&b[g][2]));
                }
        }
    }

    // Epilogue: per-head RMSNorm; warp owns a full 64-wide head.
    const int head = nblk * 2 + (wid & 1);
    const float* nw = (z ? vw : qw) + head * HD;
    float* Out = (z ? g_V : g_Q);

    float nwv[8][2];
#pragma unroll
    for (int j = 0; j < 8; j++) {
        float2 t = *(const float2*)(nw + j * 8 + 2 * (lane & 3));
        nwv[j][0] = t.x; nwv[j][1] = t.y;
    }

#pragma unroll
    for (int i = 0; i < 2; i++) {
#pragma unroll
        for (int hh = 0; hh < 2; hh++) {   // row halves: c0/c1 vs c2/c3
            float ss = 0.f;
#pragma unroll
            for (int j = 0; j < 8; j++) {
                const float v0 = acc[i][j][2 * hh];
                const float v1 = acc[i][j][2 * hh + 1];
                ss = fmaf(v0, v0, fmaf(v1, v1, ss));
            }
            ss += __shfl_xor_sync(0xffffffffu, ss, 1);
            ss += __shfl_xor_sync(0xffffffffu, ss, 2);
            const float inv = rsqrtf(ss * (1.0f / 64.0f) + 1e-8f);

            const int row = mblk * BM + mbase + i * 16 + hh * 8 + (lane >> 2);
            float* op = Out + (size_t)row * DD + head * HD + 2 * (lane & 3);
#pragma unroll
            for (int j = 0; j < 8; j++) {
                float2 o;
                o.x = acc[i][j][2 * hh]     * inv * nwv[j][0];
                o.y = acc[i][j][2 * hh + 1] * inv * nwv[j][1];
                *(float2*)(op + j * 8) = o;
            }
        }
    }
}

// ---------------------------------------------------------------------------
// Kernel B: per-chunk KV outer-product sums. S_c[d][e] = sum_t K[t][d]*V[t][e]
// ---------------------------------------------------------------------------
__global__ __launch_bounds__(256) void k_chunk_kv(const float* __restrict__ X)
{
    __shared__ float Ks[64][64];
    __shared__ float Vs[64][64];

    const int c = blockIdx.x, h = blockIdx.y, b = blockIdx.z;
    const int tid = threadIdx.x;

    const int trow = tid >> 2;
    const int toff = (tid & 3) * 16;
    const float* Kg = X   + (size_t)(b * LL + c * CH + trow) * DD + h * HD;
    const float* Vg = g_V + (size_t)(b * LL + c * CH + trow) * DD + h * HD;
#pragma unroll
    for (int q = 0; q < 4; q++) {
        *(float4*)&Ks[trow][toff + 4 * q] = *(const float4*)(Kg + toff + 4 * q);
        *(float4*)&Vs[trow][toff + 4 * q] = *(const float4*)(Vg + toff + 4 * q);
    }
    __syncthreads();

    const int ty = tid >> 4, tx = tid & 15;
    const int d0 = ty * 4, e0 = tx * 4;

    float acc[4][4];
#pragma unroll
    for (int i = 0; i < 4; i++)
#pragma unroll
        for (int j = 0; j < 4; j++) acc[i][j] = 0.f;

#pragma unroll 4
    for (int t = 0; t < 64; t++) {
        float4 a  = *(const float4*)&Ks[t][d0];
        float4 b4 = *(const float4*)&Vs[t][e0];
        const float av[4] = {a.x, a.y, a.z, a.w};
        const float bv[4] = {b4.x, b4.y, b4.z, b4.w};
#pragma unroll
        for (int i = 0; i < 4; i++)
#pragma unroll
            for (int j = 0; j < 4; j++)
                acc[i][j] = fmaf(av[i], bv[j], acc[i][j]);
    }

    float* Sp = g_S + (size_t)((b * HH + h) * NC + c) * (HD * HD);
#pragma unroll
    for (int i = 0; i < 4; i++) {
        float4 o = {acc[i][0], acc[i][1], acc[i][2], acc[i][3]};
        *(float4*)&Sp[(d0 + i) * HD + e0] = o;
    }
}

// ---------------------------------------------------------------------------
// Kernel C: EXCLUSIVE prefix sum over 16 chunks. Grid (32 bh, 16 eblocks).
// Each thread owns ONE (d,e) element across all chunks.
// ---------------------------------------------------------------------------
__global__ __launch_bounds__(256) void k_prefix()
{
    const int bh = blockIdx.x;
    const int e = blockIdx.y * 256 + threadIdx.x;
    float* base = g_S + (size_t)bh * NC * HD * HD + e;
    float run = 0.f;
#pragma unroll
    for (int c = 0; c < NC; c++) {
        const float v = base[c * (HD * HD)];
        base[c * (HD * HD)] = run;
        run += v;
    }
}

// ---------------------------------------------------------------------------
// Kernel D: per-chunk output.  O = Q @ S_prefix + causal_incl(Q @ K^T) @ V
// Stage 1+2 merged: both consume Q^T rows, feed two accumulator sets.
// ---------------------------------------------------------------------------
__global__ __launch_bounds__(256) void k_out(const float* __restrict__ X,
                                             float* __restrict__ Out)
{
    __shared__ float BufA[64][64];
    __shared__ float BufB[64][64];
    __shared__ float BufC[64][64];

    const int c = blockIdx.x, h = blockIdx.y, b = blockIdx.z;
    const int tid = threadIdx.x;

    {
        const int lrow = tid >> 2;
        const int koff = (tid & 3) * 16;
        const float* Qg = g_Q + (size_t)(b * LL + c * CH + lrow) * DD + h * HD;
        const float* Kg = X   + (size_t)(b * LL + c * CH + lrow) * DD + h * HD;
#pragma unroll
        for (int q = 0; q < 4; q++) {
            float4 v = *(const float4*)(Qg + koff + 4 * q);
            BufA[koff + 4*q + 0][lrow] = v.x; BufA[koff + 4*q + 1][lrow] = v.y;
            BufA[koff + 4*q + 2][lrow] = v.z; BufA[koff + 4*q + 3][lrow] = v.w;
            float4 w = *(const float4*)(Kg + koff + 4 * q);
            BufC[koff + 4*q + 0][lrow] = w.x; BufC[koff + 4*q + 1][lrow] = w.y;
            BufC[koff + 4*q + 2][lrow] = w.z; BufC[koff + 4*q + 3][lrow] = w.w;
        }
        const float* Sp = g_S + (size_t)((b * HH + h) * NC + c) * (HD * HD);
#pragma unroll
        for (int j = 0; j < 4; j++) {
            const int idx = tid + j * 256;
            ((float4*)&BufB[0][0])[idx] = ((const float4*)Sp)[idx];
        }
    }
    __syncthreads();

    const int ty = tid >> 4, tx = tid & 15;
    const int l0 = ty * 4;
    const int e0 = tx * 4;

    float O[4][4], A[4][4];
#pragma unroll
    for (int i = 0; i < 4; i++)
#pragma unroll
        for (int j = 0; j < 4; j++) { O[i][j] = 0.f; A[i][j] = 0.f; }

    // Merged: O += Q @ S_prefix  and  A += Q @ K^T  (shared Q operand)
#pragma unroll 2
    for (int k = 0; k < 64; k++) {
        float4 a  = *(const float4*)&BufA[k][l0];
        float4 bS = *(const float4*)&BufB[k][e0];
        float4 bK = *(const float4*)&BufC[k][e0];
        const float av[4] = {a.x, a.y, a.z, a.w};
        const float sv[4] = {bS.x, bS.y, bS.z, bS.w};
        const float kv[4] = {bK.x, bK.y, bK.z, bK.w};
#pragma unroll
        for (int i = 0; i < 4; i++)
#pragma unroll
            for (int j = 0; j < 4; j++) {
                O[i][j] = fmaf(av[i], sv[j], O[i][j]);
                A[i][j] = fmaf(av[i], kv[j], A[i][j]);
            }
    }
#pragma unroll
    for (int i = 0; i < 4; i++)
#pragma unroll
        for (int j = 0; j < 4; j++)
            if (e0 + j > l0 + i) A[i][j] = 0.f;   // keep t <= l (inclusive)

    __syncthreads();   // done reading BufA (Q) and BufB (S)

    // Store A into BufA natural [l][t]; load V into BufB natural [t][e]
#pragma unroll
    for (int i = 0; i < 4; i++)
#pragma unroll
        for (int j = 0; j < 4; j++)
            BufA[l0 + i][e0 + j] = A[i][j];
    {
        const int trow = tid >> 2;
        const int eoff = (tid & 3) * 16;
        const float* Vg = g_V + (size_t)(b * LL + c * CH + trow) * DD + h * HD;
#pragma unroll
        for (int q = 0; q < 4; q++)
            *(float4*)&BufB[trow][eoff + 4 * q] = *(const float4*)(Vg + eoff + 4 * q);
    }
    __syncthreads();

    // O += A @ V
#pragma unroll 4
    for (int t = 0; t < 64; t++) {
        const float av[4] = {BufA[l0 + 0][t], BufA[l0 + 1][t],
                             BufA[l0 + 2][t], BufA[l0 + 3][t]};
        float4 b4 = *(const float4*)&BufB[t][e0];
        const float bv[4] = {b4.x, b4.y, b4.z, b4.w};
#pragma unroll
        for (int i = 0; i < 4; i++)
#pragma unroll
            for (int j = 0; j < 4; j++)
                O[i][j] = fmaf(av[i], bv[j], O[i][j]);
    }

    float* Op = Out + (size_t)(b * LL + c * CH) * DD + h * HD;
#pragma unroll
    for (int i = 0; i < 4; i++) {
        float4 o = {O[i][0], O[i][1], O[i][2], O[i][3]};
        *(float4*)&Op[(size_t)(l0 + i) * DD + e0] = o;
    }
}

// ---------------------------------------------------------------------------
extern "C" void kernel_launch(void* const* d_in, const int* in_sizes, int n_in,
                              void* d_out, int out_size)
{
    const float* X  = (const float*)d_in[0];
    const float* Wq = (const float*)d_in[1];
    const float* Wv = (const float*)d_in[2];
    const float* qw = (const float*)d_in[3];
    const float* vw = (const float*)d_in[4];
    float* Out = (float*)d_out;

    const int SMEM_PROJ = 2 * NSTAGE * ASZ;  // 110592 bytes
    cudaFuncSetAttribute(k_proj, cudaFuncAttributeMaxDynamicSharedMemorySize,
                         SMEM_PROJ);

    k_split   <<<dim3(1024, 1, 3), 256>>>(X, Wq, Wv);
    k_proj    <<<dim3(16, 8, 2), 256, SMEM_PROJ>>>(qw, vw);
    k_chunk_kv<<<dim3(16, 16, 2), 256>>>(X);
    k_prefix  <<<dim3(32, 16), 256>>>();
    k_out     <<<dim3(16, 16, 2), 256>>>(X, Out);
}

// round 6
// speedup vs baseline: 2.3694x; 1.1275x over previous
#include <cuda_runtime.h>
#include <cuda_bf16.h>
#include <cstdint>
#include <cstring>

// Problem constants (fixed shapes from reference)
#define BB   2
#define LL   1024
#define DD   1024
#define HH   16
#define HD   64      // head dim
#define NC   16      // number of chunks per sequence
#define CH   64      // chunk length
#define MTOT (BB*LL) // 2048 rows

// Projection GEMM: bf16x3 split, K' = 3*D
#define KT2  3072
#define BK   64
#define GITER (KT2/BK)    // 48
#define BM   128
#define BN   128
#define ROWB 144          // padded smem row stride in bytes (64 bf16 + 8 pad)
#define ASZ  (128*ROWB)   // 18432 bytes per tile buffer
#define NSTAGE 3

// Scratch (no allocations allowed in kernel_launch)
__device__ float g_Q[MTOT * DD];                 // 8 MB : normalized Q
__device__ float g_V[MTOT * DD];                 // 8 MB : normalized V
__device__ float g_S[BB * HH * NC * HD * HD];    // 8 MB : per-chunk S^T sums
__device__ __nv_bfloat16 g_Ax [MTOT * KT2];      // 12 MB : [Xhi | Xlo | Xhi]
__device__ __nv_bfloat16 g_Wq2[DD * KT2];        // 6 MB  : [Whi | Whi | Wlo]
__device__ __nv_bfloat16 g_Wv2[DD * KT2];        // 6 MB

static __device__ __forceinline__ uint32_t s2u(const void* p) {
    uint32_t a;
    asm("{ .reg .u64 t; cvta.to.shared.u64 t, %1; cvt.u32.u64 %0, t; }"
        : "=r"(a) : "l"(p));
    return a;
}
static __device__ __forceinline__ uint32_t b2u(__nv_bfloat162 v) {
    uint32_t u; memcpy(&u, &v, 4); return u;
}

#define CP_ASYNC16(saddr, gptr) \
    asm volatile("cp.async.cg.shared.global [%0], [%1], 16;" \
                 :: "r"(saddr), "l"(gptr))
#define CP_COMMIT() asm volatile("cp.async.commit_group;")
#define CP_WAIT(n)  asm volatile("cp.async.wait_group %0;" :: "n"(n))

#define LDMATRIX_X4(r0, r1, r2, r3, addr) \
    asm volatile("ldmatrix.sync.aligned.m8n8.x4.shared.b16 {%0,%1,%2,%3}, [%4];" \
                 : "=r"(r0), "=r"(r1), "=r"(r2), "=r"(r3) : "r"(addr))

#define MMA16816(d, a, b) \
    asm volatile("mma.sync.aligned.m16n8k16.row.col.f32.bf16.bf16.f32 " \
                 "{%0,%1,%2,%3}, {%4,%5,%6,%7}, {%8,%9}, {%0,%1,%2,%3};" \
                 : "+f"((d)[0]), "+f"((d)[1]), "+f"((d)[2]), "+f"((d)[3]) \
                 : "r"((a)[0]), "r"((a)[1]), "r"((a)[2]), "r"((a)[3]),   \
                   "r"((b)[0]), "r"((b)[1]))

// ---------------------------------------------------------------------------
// fp32 64x64 -> bf16 hi/lo into XOR-swizzled smem (128B rows, chunk^(row&7)).
// natural: dst row = src row (+rowoff), dst col = src col.
// ---------------------------------------------------------------------------
static __device__ __forceinline__ void conv_nat64(
    const float* __restrict__ src, int stride, char* dhi, char* dlo,
    int rowoff, int tid)
{
#pragma unroll
    for (int p = 0; p < 8; p++) {
        const int f = tid + p * 128;
        const int r = f >> 4, cc = (f & 15) * 4;
        float4 v = *(const float4*)(src + (size_t)r * stride + cc);
        float vs[4] = {v.x, v.y, v.z, v.w};
        __nv_bfloat16 h[4], l[4];
#pragma unroll
        for (int i = 0; i < 4; i++) {
            h[i] = __float2bfloat16(vs[i]);
            l[i] = __float2bfloat16(vs[i] - __bfloat162float(h[i]));
        }
        uint2 H = { b2u(__halves2bfloat162(h[0], h[1])),
                    b2u(__halves2bfloat162(h[2], h[3])) };
        uint2 L = { b2u(__halves2bfloat162(l[0], l[1])),
                    b2u(__halves2bfloat162(l[2], l[3])) };
        const int row = r + rowoff;
        const int off = row * 128 + (((cc >> 3) ^ (row & 7)) << 4) + (cc & 7) * 2;
        *(uint2*)(dhi + off) = H;
        *(uint2*)(dlo + off) = L;
    }
}

// transposed: dst row = src col, dst col = src row.
static __device__ __forceinline__ void conv_tr64(
    const float* __restrict__ src, int stride, char* dhi, char* dlo, int tid)
{
#pragma unroll
    for (int p = 0; p < 8; p++) {
        const int f = tid + p * 128;
        const int r = f >> 4, cc = (f & 15) * 4;
        float4 v = *(const float4*)(src + (size_t)r * stride + cc);
        float vs[4] = {v.x, v.y, v.z, v.w};
#pragma unroll
        for (int i = 0; i < 4; i++) {
            __nv_bfloat16 hi = __float2bfloat16(vs[i]);
            __nv_bfloat16 lo = __float2bfloat16(vs[i] - __bfloat162float(hi));
            const int row = cc + i, col = r;
            const int off = row * 128 + (((col >> 3) ^ (row & 7)) << 4)
                          + (col & 7) * 2;
            *(__nv_bfloat16*)(dhi + off) = hi;
            *(__nv_bfloat16*)(dlo + off) = lo;
        }
    }
}

// ---------------------------------------------------------------------------
// Kernel S: fp32 -> bf16x3 split along K.  8 elements/thread, 16B stores.
// ---------------------------------------------------------------------------
__global__ __launch_bounds__(256) void k_split(
    const float* __restrict__ X, const float* __restrict__ Wq,
    const float* __restrict__ Wv)
{
    const int z = blockIdx.z;
    const float* src = (z == 0) ? X : (z == 1) ? Wq : Wv;
    __nv_bfloat16* dst = (z == 0) ? g_Ax : (z == 1) ? g_Wq2 : g_Wv2;
    const int rows = (z == 0) ? MTOT : DD;

    const int gid = blockIdx.x * 256 + threadIdx.x;
    const int idx8 = gid * 8;
    if (idx8 >= rows * DD) return;
    const int row = idx8 >> 10;
    const int col = idx8 & 1023;

    const float* sp = src + (size_t)row * DD + col;
    float4 v0 = *(const float4*)(sp);
    float4 v1 = *(const float4*)(sp + 4);
    float vs[8] = {v0.x, v0.y, v0.z, v0.w, v1.x, v1.y, v1.z, v1.w};
    __nv_bfloat16 h[8], l[8];
#pragma unroll
    for (int i = 0; i < 8; i++) {
        h[i] = __float2bfloat16(vs[i]);
        l[i] = __float2bfloat16(vs[i] - __bfloat162float(h[i]));
    }
    uint4 HU, LU;
    HU.x = b2u(__halves2bfloat162(h[0], h[1]));
    HU.y = b2u(__halves2bfloat162(h[2], h[3]));
    HU.z = b2u(__halves2bfloat162(h[4], h[5]));
    HU.w = b2u(__halves2bfloat162(h[6], h[7]));
    LU.x = b2u(__halves2bfloat162(l[0], l[1]));
    LU.y = b2u(__halves2bfloat162(l[2], l[3]));
    LU.z = b2u(__halves2bfloat162(l[4], l[5]));
    LU.w = b2u(__halves2bfloat162(l[6], l[7]));

    __nv_bfloat16* base = dst + (size_t)row * KT2 + col;
    *(uint4*)(base) = HU;                                 // seg0 = hi
    *(uint4*)(base + DD)     = (z == 0) ? LU : HU;        // seg1
    *(uint4*)(base + 2 * DD) = (z == 0) ? HU : LU;        // seg2
}

// ---------------------------------------------------------------------------
// Kernel P: projection GEMM via mma.sync (HMMA) + fused per-head RMSNorm.
// (unchanged from R5 — at the SIMT HMMA issue floor)
// ---------------------------------------------------------------------------
__global__ __launch_bounds__(256, 2) void k_proj(
    const float* __restrict__ qw, const float* __restrict__ vw)
{
    extern __shared__ char smem[];
    const int tid = threadIdx.x, wid = tid >> 5, lane = tid & 31;
    const int mblk = blockIdx.x, nblk = blockIdx.y, z = blockIdx.z;

    const uint32_t sA0 = s2u(smem);
    const uint32_t sB0 = sA0 + NSTAGE * ASZ;

    const __nv_bfloat16* Ag = g_Ax + (size_t)mblk * BM * KT2;
    const __nv_bfloat16* Bg = (z ? g_Wv2 : g_Wq2) + (size_t)nblk * BN * KT2;

    const int ldrow = tid >> 3;
    const int ldch  = tid & 7;

    auto load_tile = [&](int buf, int k0) {
        const uint32_t a = sA0 + buf * ASZ;
        const uint32_t b = sB0 + buf * ASZ;
#pragma unroll
        for (int j = 0; j < 4; j++) {
            const int row = ldrow + j * 32;
            CP_ASYNC16(a + row * ROWB + ldch * 16,
                       Ag + (size_t)row * KT2 + k0 + ldch * 8);
        }
#pragma unroll
        for (int j = 0; j < 4; j++) {
            const int row = ldrow + j * 32;
            CP_ASYNC16(b + row * ROWB + ldch * 16,
                       Bg + (size_t)row * KT2 + k0 + ldch * 8);
        }
        CP_COMMIT();
    };

    float acc[2][8][4];
#pragma unroll
    for (int i = 0; i < 2; i++)
#pragma unroll
        for (int j = 0; j < 8; j++)
#pragma unroll
            for (int q = 0; q < 4; q++) acc[i][j][q] = 0.f;

    const int mbase = (wid >> 1) * 32;
    const int nbase = (wid & 1) * 64;

    const int a_row = (lane & 15);
    const int a_off = (lane >> 4) * 16;
    const int b_row = ((lane >> 4) << 3) + (lane & 7);
    const int b_off = ((lane >> 3) & 1) * 16;

    load_tile(0, 0);
    load_tile(1, BK);

#pragma unroll 1
    for (int it = 0; it < GITER; it++) {
        const int buf = it % NSTAGE;
        CP_WAIT(1);
        __syncthreads();
        if (it + 2 < GITER) load_tile((it + 2) % NSTAGE, (it + 2) * BK);

        const uint32_t sAb = sA0 + buf * ASZ;
        const uint32_t sBb = sB0 + buf * ASZ;
#pragma unroll
        for (int k16 = 0; k16 < 4; k16++) {
            uint32_t a[2][4];
#pragma unroll
            for (int i = 0; i < 2; i++) {
                const uint32_t addr = sAb
                    + (mbase + i * 16 + a_row) * ROWB + k16 * 32 + a_off;
                LDMATRIX_X4(a[i][0], a[i][1], a[i][2], a[i][3], addr);
            }
            uint32_t b[4][4];
#pragma unroll
            for (int g = 0; g < 4; g++) {
                const uint32_t addr = sBb
                    + (nbase + g * 16 + b_row) * ROWB + k16 * 32 + b_off;
                LDMATRIX_X4(b[g][0], b[g][1], b[g][2], b[g][3], addr);
            }
#pragma unroll
            for (int i = 0; i < 2; i++)
#pragma unroll
                for (int g = 0; g < 4; g++) {
                    MMA16816(acc[i][2 * g],     a[i], (&b[g][0]));
                    MMA16816(acc[i][2 * g + 1], a[i], (&b[g][2]));
                }
        }
    }

    const int head = nblk * 2 + (wid & 1);
    const float* nw = (z ? vw : qw) + head * HD;
    float* Out = (z ? g_V : g_Q);

    float nwv[8][2];
#pragma unroll
    for (int j = 0; j < 8; j++) {
        float2 t = *(const float2*)(nw + j * 8 + 2 * (lane & 3));
        nwv[j][0] = t.x; nwv[j][1] = t.y;
    }

#pragma unroll
    for (int i = 0; i < 2; i++) {
#pragma unroll
        for (int hh = 0; hh < 2; hh++) {
            float ss = 0.f;
#pragma unroll
            for (int j = 0; j < 8; j++) {
                const float v0 = acc[i][j][2 * hh];
                const float v1 = acc[i][j][2 * hh + 1];
                ss = fmaf(v0, v0, fmaf(v1, v1, ss));
            }
            ss += __shfl_xor_sync(0xffffffffu, ss, 1);
            ss += __shfl_xor_sync(0xffffffffu, ss, 2);
            const float inv = rsqrtf(ss * (1.0f / 64.0f) + 1e-8f);

            const int row = mblk * BM + mbase + i * 16 + hh * 8 + (lane >> 2);
            float* op = Out + (size_t)row * DD + head * HD + 2 * (lane & 3);
#pragma unroll
            for (int j = 0; j < 8; j++) {
                float2 o;
                o.x = acc[i][j][2 * hh]     * inv * nwv[j][0];
                o.y = acc[i][j][2 * hh + 1] * inv * nwv[j][1];
                *(float2*)(op + j * 8) = o;
            }
        }
    }
}

// ---------------------------------------------------------------------------
// Kernel B (HMMA): per-chunk S^T[e][d] = sum_t V[t][e] * K[t][d].
// A = V^T (rows e), B = K^T (rows d), bf16x3. 128 threads, 4 warps (16 rows ea).
// ---------------------------------------------------------------------------
__global__ __launch_bounds__(128) void k_chunk_kv(const float* __restrict__ X)
{
    extern __shared__ char sm[];
    const int c = blockIdx.x, h = blockIdx.y, b = blockIdx.z;
    const int tid = threadIdx.x, wid = tid >> 5, lane = tid & 31;

    char* VThi = sm;            // 8KB each
    char* VTlo = sm + 8192;
    char* KThi = sm + 16384;
    char* KTlo = sm + 24576;

    const float* Kg = X   + ((size_t)(b * LL + c * CH)) * DD + h * HD;
    const float* Vg = g_V + ((size_t)(b * LL + c * CH)) * DD + h * HD;

    conv_tr64(Vg, DD, VThi, VTlo, tid);
    conv_tr64(Kg, DD, KThi, KTlo, tid);
    __syncthreads();

    const uint32_t uVThi = s2u(VThi), uVTlo = s2u(VTlo);
    const uint32_t uKThi = s2u(KThi), uKTlo = s2u(KTlo);
    const int mbase = wid * 16;
    const int arow = mbase + (lane & 15);

    float acc[8][4];
#pragma unroll
    for (int j = 0; j < 8; j++)
#pragma unroll
        for (int q = 0; q < 4; q++) acc[j][q] = 0.f;

#pragma unroll
    for (int s = 0; s < 3; s++) {
        const uint32_t Ab = (s == 1) ? uVTlo : uVThi;   // A pattern [hi|lo|hi]
        const uint32_t Bb = (s == 2) ? uKTlo : uKThi;   // B pattern [hi|hi|lo]
#pragma unroll
        for (int k16 = 0; k16 < 4; k16++) {
            uint32_t a[4];
            LDMATRIX_X4(a[0], a[1], a[2], a[3],
                Ab + arow * 128 + (((2 * k16 + (lane >> 4)) ^ (lane & 7)) << 4));
#pragma unroll
            for (int g = 0; g < 4; g++) {
                const int grow = g * 16 + ((lane >> 4) << 3) + (lane & 7);
                uint32_t bb[4];
                LDMATRIX_X4(bb[0], bb[1], bb[2], bb[3],
                    Bb + grow * 128
                    + (((2 * k16 + ((lane >> 3) & 1)) ^ (lane & 7)) << 4));
                MMA16816(acc[2 * g],     a, bb);
                MMA16816(acc[2 * g + 1], a, (bb + 2));
            }
        }
    }

    float* Sp = g_S + (size_t)((b * HH + h) * NC + c) * (HD * HD);
#pragma unroll
    for (int j = 0; j < 8; j++)
#pragma unroll
        for (int hh = 0; hh < 2; hh++) {
            const int e = mbase + (lane >> 2) + 8 * hh;
            const int d = 8 * j + 2 * (lane & 3);
            float2 o = {acc[j][2 * hh], acc[j][2 * hh + 1]};
            *(float2*)(Sp + e * HD + d) = o;
        }
}

// ---------------------------------------------------------------------------
// Kernel C: EXCLUSIVE prefix sum over 16 chunks (elementwise on S^T).
// ---------------------------------------------------------------------------
__global__ __launch_bounds__(256) void k_prefix()
{
    const int bh = blockIdx.x;
    const int e = blockIdx.y * 256 + threadIdx.x;
    float* base = g_S + (size_t)bh * NC * HD * HD + e;
    float run = 0.f;
#pragma unroll
    for (int c = 0; c < NC; c++) {
        const float v = base[c * (HD * HD)];
        base[c * (HD * HD)] = run;
        run += v;
    }
}

// ---------------------------------------------------------------------------
// Kernel D (HMMA): per-chunk output. 128 threads, 4 warps (16 rows each).
//   GEMM1: [O1 | A] = Q @ [S^T-rows | K]   (N=128, causal skip in A region)
//   mask A, re-split hi/lo, GEMM2: O = O1 + A @ V^T
// smem: Qhi/Qlo (16KB) + B1hi/B1lo (32KB); phase B aliases B1 with A2 + VT.
// ---------------------------------------------------------------------------
__global__ __launch_bounds__(128) void k_out(const float* __restrict__ X,
                                             float* __restrict__ Out)
{
    extern __shared__ char sm[];
    const int c = blockIdx.x, h = blockIdx.y, b = blockIdx.z;
    const int tid = threadIdx.x, wid = tid >> 5, lane = tid & 31;

    char* Qhi = sm;             // 8KB
    char* Qlo = sm + 8192;
    char* B1hi = sm + 16384;    // 16KB : rows 0-63 = S^T, rows 64-127 = K
    char* B1lo = sm + 32768;
    // phase B aliases (B1 dead after GEMM1)
    char* A2hi = sm + 16384;
    char* A2lo = sm + 24576;
    char* VThi = sm + 32768;
    char* VTlo = sm + 40960;

    const float* Qg = g_Q + ((size_t)(b * LL + c * CH)) * DD + h * HD;
    const float* Kg = X   + ((size_t)(b * LL + c * CH)) * DD + h * HD;
    const float* Vg = g_V + ((size_t)(b * LL + c * CH)) * DD + h * HD;
    const float* Sp = g_S + (size_t)((b * HH + h) * NC + c) * (HD * HD);

    conv_nat64(Qg, DD, Qhi, Qlo, 0, tid);
    conv_nat64(Sp, HD, B1hi, B1lo, 0, tid);    // S^T rows are natural
    conv_nat64(Kg, DD, B1hi, B1lo, 64, tid);
    __syncthreads();

    const uint32_t uQhi = s2u(Qhi), uQlo = s2u(Qlo);
    const uint32_t uB1hi = s2u(B1hi), uB1lo = s2u(B1lo);
    const int mbase = wid * 16;
    const int arow = mbase + (lane & 15);

    float acc[16][4];
#pragma unroll
    for (int j = 0; j < 16; j++)
#pragma unroll
        for (int q = 0; q < 4; q++) acc[j][q] = 0.f;

    // GEMM1
#pragma unroll
    for (int s = 0; s < 3; s++) {
        const uint32_t Ab = (s == 1) ? uQlo : uQhi;
        const uint32_t Bb = (s == 2) ? uB1lo : uB1hi;
#pragma unroll
        for (int k16 = 0; k16 < 4; k16++) {
            uint32_t a[4];
            LDMATRIX_X4(a[0], a[1], a[2], a[3],
                Ab + arow * 128 + (((2 * k16 + (lane >> 4)) ^ (lane & 7)) << 4));
#pragma unroll
            for (int g = 0; g < 8; g++) {
                if (g >= 4 && (g - 4) > wid) continue;  // fully-masked A tiles
                const int grow = g * 16 + ((lane >> 4) << 3) + (lane & 7);
                uint32_t bb[4];
                LDMATRIX_X4(bb[0], bb[1], bb[2], bb[3],
                    Bb + grow * 128
                    + (((2 * k16 + ((lane >> 3) & 1)) ^ (lane & 7)) << 4));
                MMA16816(acc[2 * g],     a, bb);
                MMA16816(acc[2 * g + 1], a, (bb + 2));
            }
        }
    }

    __syncthreads();   // B1 reads complete; safe to overwrite with A2/VT

    // Causal mask + re-split A into smem (covers all rows/cols; masked -> 0)
#pragma unroll
    for (int j = 8; j < 16; j++)
#pragma unroll
        for (int q = 0; q < 4; q++) {
            const int t = (j - 8) * 8 + 2 * (lane & 3) + (q & 1);
            const int l = mbase + (lane >> 2) + 8 * (q >> 1);
            const float v = (t <= l) ? acc[j][q] : 0.f;
            const __nv_bfloat16 hi = __float2bfloat16(v);
            const __nv_bfloat16 lo =
                __float2bfloat16(v - __bfloat162float(hi));
            const int off = l * 128 + (((t >> 3) ^ (l & 7)) << 4) + (t & 7) * 2;
            *(__nv_bfloat16*)(A2hi + off) = hi;
            *(__nv_bfloat16*)(A2lo + off) = lo;
        }

    conv_tr64(Vg, DD, VThi, VTlo, tid);   // V^T rows e, cols t
    __syncthreads();

    const uint32_t uA2hi = s2u(A2hi), uA2lo = s2u(A2lo);
    const uint32_t uVThi = s2u(VThi), uVTlo = s2u(VTlo);

    // GEMM2: O(acc[0..7]) += A @ V^T
#pragma unroll
    for (int s = 0; s < 3; s++) {
        const uint32_t Ab = (s == 1) ? uA2lo : uA2hi;
        const uint32_t Bb = (s == 2) ? uVTlo : uVThi;
#pragma unroll
        for (int k16 = 0; k16 < 4; k16++) {
            uint32_t a[4];
            LDMATRIX_X4(a[0], a[1], a[2], a[3],
                Ab + arow * 128 + (((2 * k16 + (lane >> 4)) ^ (lane & 7)) << 4));
#pragma unroll
            for (int g = 0; g < 4; g++) {
                const int grow = g * 16 + ((lane >> 4) << 3) + (lane & 7);
                uint32_t bb[4];
                LDMATRIX_X4(bb[0], bb[1], bb[2], bb[3],
                    Bb + grow * 128
                    + (((2 * k16 + ((lane >> 3) & 1)) ^ (lane & 7)) << 4));
                MMA16816(acc[2 * g],     a, bb);
                MMA16816(acc[2 * g + 1], a, (bb + 2));
            }
        }
    }

    // Write O
    float* Op = Out + ((size_t)(b * LL + c * CH)) * DD + h * HD;
#pragma unroll
    for (int j = 0; j < 8; j++)
#pragma unroll
        for (int hh = 0; hh < 2; hh++) {
            const int l = mbase + (lane >> 2) + 8 * hh;
            const int e = 8 * j + 2 * (lane & 3);
            float2 o = {acc[j][2 * hh], acc[j][2 * hh + 1]};
            *(float2*)(Op + (size_t)l * DD + e) = o;
        }
}

// ---------------------------------------------------------------------------
extern "C" void kernel_launch(void* const* d_in, const int* in_sizes, int n_in,
                              void* d_out, int out_size)
{
    const float* X  = (const float*)d_in[0];
    const float* Wq = (const float*)d_in[1];
    const float* Wv = (const float*)d_in[2];
    const float* qw = (const float*)d_in[3];
    const float* vw = (const float*)d_in[4];
    float* Out = (float*)d_out;

    const int SMEM_PROJ = 2 * NSTAGE * ASZ;  // 110592 bytes
    cudaFuncSetAttribute(k_proj, cudaFuncAttributeMaxDynamicSharedMemorySize,
                         SMEM_PROJ);
    cudaFuncSetAttribute(k_out, cudaFuncAttributeMaxDynamicSharedMemorySize,
                         49152);
    cudaFuncSetAttribute(k_chunk_kv,
                         cudaFuncAttributeMaxDynamicSharedMemorySize, 32768);

    k_split   <<<dim3(1024, 1, 3), 256>>>(X, Wq, Wv);
    k_proj    <<<dim3(16, 8, 2), 256, SMEM_PROJ>>>(qw, vw);
    k_chunk_kv<<<dim3(16, 16, 2), 128, 32768>>>(X);
    k_prefix  <<<dim3(32, 16), 256>>>();
    k_out     <<<dim3(16, 16, 2), 128, 49152>>>(X, Out);
}

// round 7
// speedup vs baseline: 3.0787x; 1.2994x over previous
#include <cuda_runtime.h>
#include <cuda_bf16.h>
#include <cuda_fp16.h>
#include <cstdint>
#include <cstring>

// Problem constants (fixed shapes from reference)
#define BB   2
#define LL   1024
#define DD   1024
#define HH   16
#define HD   64      // head dim
#define NC   16      // number of chunks per sequence
#define CH   64      // chunk length
#define MTOT (BB*LL) // 2048 rows

// Projection GEMM: fp16 2-term split, K' = 2*D
// A' = [Ahi | Alo] (fp16),  B' = [Bhi | Bhi] (fp16)
//  =>  A'.B' = (Ahi+Alo).Bhi ; dropped term A.(B-Bhi) ~ 2^-12 relative.
#define KTP  2048
#define BK   64
#define GITER (KTP/BK)    // 32
#define BM   128
#define BN   128
#define ROWB 144          // padded smem row stride in bytes (64 x 2B + 16 pad)
#define ASZ  (128*ROWB)   // 18432 bytes per tile buffer
#define NSTAGE 3

// Scratch (no allocations allowed in kernel_launch)
__device__ float g_Q[MTOT * DD];                 // 8 MB : normalized Q
__device__ float g_V[MTOT * DD];                 // 8 MB : normalized V
__device__ float g_S[BB * HH * NC * HD * HD];    // 8 MB : per-chunk S^T sums
__device__ __half g_Ax [MTOT * KTP];             // 8 MB : [Xhi | Xlo]
__device__ __half g_Wq2[DD * KTP];               // 4 MB : [Whi | Whi]
__device__ __half g_Wv2[DD * KTP];               // 4 MB

static __device__ __forceinline__ uint32_t s2u(const void* p) {
    uint32_t a;
    asm("{ .reg .u64 t; cvta.to.shared.u64 t, %1; cvt.u32.u64 %0, t; }"
        : "=r"(a) : "l"(p));
    return a;
}
static __device__ __forceinline__ uint32_t b2u(__nv_bfloat162 v) {
    uint32_t u; memcpy(&u, &v, 4); return u;
}
static __device__ __forceinline__ uint32_t h2u(__half2 v) {
    uint32_t u; memcpy(&u, &v, 4); return u;
}

#define CP_ASYNC16(saddr, gptr) \
    asm volatile("cp.async.cg.shared.global [%0], [%1], 16;" \
                 :: "r"(saddr), "l"(gptr))
#define CP_COMMIT() asm volatile("cp.async.commit_group;")
#define CP_WAIT(n)  asm volatile("cp.async.wait_group %0;" :: "n"(n))

#define LDMATRIX_X4(r0, r1, r2, r3, addr) \
    asm volatile("ldmatrix.sync.aligned.m8n8.x4.shared.b16 {%0,%1,%2,%3}, [%4];" \
                 : "=r"(r0), "=r"(r1), "=r"(r2), "=r"(r3) : "r"(addr))

// bf16 MMA (attention kernels)
#define MMA16816(d, a, b) \
    asm volatile("mma.sync.aligned.m16n8k16.row.col.f32.bf16.bf16.f32 " \
                 "{%0,%1,%2,%3}, {%4,%5,%6,%7}, {%8,%9}, {%0,%1,%2,%3};" \
                 : "+f"((d)[0]), "+f"((d)[1]), "+f"((d)[2]), "+f"((d)[3]) \
                 : "r"((a)[0]), "r"((a)[1]), "r"((a)[2]), "r"((a)[3]),   \
                   "r"((b)[0]), "r"((b)[1]))

// fp16 MMA (projection)
#define MMA16816F(d, a, b) \
    asm volatile("mma.sync.aligned.m16n8k16.row.col.f32.f16.f16.f32 " \
                 "{%0,%1,%2,%3}, {%4,%5,%6,%7}, {%8,%9}, {%0,%1,%2,%3};" \
                 : "+f"((d)[0]), "+f"((d)[1]), "+f"((d)[2]), "+f"((d)[3]) \
                 : "r"((a)[0]), "r"((a)[1]), "r"((a)[2]), "r"((a)[3]),   \
                   "r"((b)[0]), "r"((b)[1]))

// ---------------------------------------------------------------------------
// fp32 64x64 -> bf16 hi/lo into XOR-swizzled smem (128B rows, chunk^(row&7)).
// natural: dst row = src row (+rowoff), dst col = src col.
// ---------------------------------------------------------------------------
static __device__ __forceinline__ void conv_nat64(
    const float* __restrict__ src, int stride, char* dhi, char* dlo,
    int rowoff, int tid)
{
#pragma unroll
    for (int p = 0; p < 8; p++) {
        const int f = tid + p * 128;
        const int r = f >> 4, cc = (f & 15) * 4;
        float4 v = *(const float4*)(src + (size_t)r * stride + cc);
        float vs[4] = {v.x, v.y, v.z, v.w};
        __nv_bfloat16 h[4], l[4];
#pragma unroll
        for (int i = 0; i < 4; i++) {
            h[i] = __float2bfloat16(vs[i]);
            l[i] = __float2bfloat16(vs[i] - __bfloat162float(h[i]));
        }
        uint2 H = { b2u(__halves2bfloat162(h[0], h[1])),
                    b2u(__halves2bfloat162(h[2], h[3])) };
        uint2 L = { b2u(__halves2bfloat162(l[0], l[1])),
                    b2u(__halves2bfloat162(l[2], l[3])) };
        const int row = r + rowoff;
        const int off = row * 128 + (((cc >> 3) ^ (row & 7)) << 4) + (cc & 7) * 2;
        *(uint2*)(dhi + off) = H;
        *(uint2*)(dlo + off) = L;
    }
}

// transposed: dst row = src col, dst col = src row.
static __device__ __forceinline__ void conv_tr64(
    const float* __restrict__ src, int stride, char* dhi, char* dlo, int tid)
{
#pragma unroll
    for (int p = 0; p < 8; p++) {
        const int f = tid + p * 128;
        const int r = f >> 4, cc = (f & 15) * 4;
        float4 v = *(const float4*)(src + (size_t)r * stride + cc);
        float vs[4] = {v.x, v.y, v.z, v.w};
#pragma unroll
        for (int i = 0; i < 4; i++) {
            __nv_bfloat16 hi = __float2bfloat16(vs[i]);
            __nv_bfloat16 lo = __float2bfloat16(vs[i] - __bfloat162float(hi));
            const int row = cc + i, col = r;
            const int off = row * 128 + (((col >> 3) ^ (row & 7)) << 4)
                          + (col & 7) * 2;
            *(__nv_bfloat16*)(dhi + off) = hi;
            *(__nv_bfloat16*)(dlo + off) = lo;
        }
    }
}

// ---------------------------------------------------------------------------
// Kernel S: fp32 -> fp16 2-term split along K.  8 elements/thread.
// z=0: X -> g_Ax as [hi | lo];  z=1/2: W -> g_W*2 as [hi | hi].
// ---------------------------------------------------------------------------
__global__ __launch_bounds__(256) void k_split(
    const float* __restrict__ X, const float* __restrict__ Wq,
    const float* __restrict__ Wv)
{
    const int z = blockIdx.z;
    const float* src = (z == 0) ? X : (z == 1) ? Wq : Wv;
    __half* dst = (z == 0) ? g_Ax : (z == 1) ? g_Wq2 : g_Wv2;
    const int rows = (z == 0) ? MTOT : DD;

    const int gid = blockIdx.x * 256 + threadIdx.x;
    const int idx8 = gid * 8;
    if (idx8 >= rows * DD) return;
    const int row = idx8 >> 10;
    const int col = idx8 & 1023;

    const float* sp = src + (size_t)row * DD + col;
    float4 v0 = *(const float4*)(sp);
    float4 v1 = *(const float4*)(sp + 4);
    float vs[8] = {v0.x, v0.y, v0.z, v0.w, v1.x, v1.y, v1.z, v1.w};
    __half h[8], l[8];
#pragma unroll
    for (int i = 0; i < 8; i++) {
        h[i] = __float2half_rn(vs[i]);
        l[i] = __float2half_rn(vs[i] - __half2float(h[i]));
    }
    uint4 HU, LU;
    HU.x = h2u(__halves2half2(h[0], h[1]));
    HU.y = h2u(__halves2half2(h[2], h[3]));
    HU.z = h2u(__halves2half2(h[4], h[5]));
    HU.w = h2u(__halves2half2(h[6], h[7]));
    LU.x = h2u(__halves2half2(l[0], l[1]));
    LU.y = h2u(__halves2half2(l[2], l[3]));
    LU.z = h2u(__halves2half2(l[4], l[5]));
    LU.w = h2u(__halves2half2(l[6], l[7]));

    __half* base = dst + (size_t)row * KTP + col;
    *(uint4*)(base) = HU;                           // seg0 = hi
    *(uint4*)(base + DD) = (z == 0) ? LU : HU;      // seg1 = lo (A) / hi (B)
}

// ---------------------------------------------------------------------------
// Kernel P: projection GEMM via fp16 mma.sync + fused per-head RMSNorm.
// 3-stage cp.async pipeline; grid (16 m, 8 n, 2 {Q,V}); 8 warps, 32x64/warp.
// ---------------------------------------------------------------------------
__global__ __launch_bounds__(256, 2) void k_proj(
    const float* __restrict__ qw, const float* __restrict__ vw)
{
    extern __shared__ char smem[];
    const int tid = threadIdx.x, wid = tid >> 5, lane = tid & 31;
    const int mblk = blockIdx.x, nblk = blockIdx.y, z = blockIdx.z;

    const uint32_t sA0 = s2u(smem);
    const uint32_t sB0 = sA0 + NSTAGE * ASZ;

    const __half* Ag = g_Ax + (size_t)mblk * BM * KTP;
    const __half* Bg = (z ? g_Wv2 : g_Wq2) + (size_t)nblk * BN * KTP;

    const int ldrow = tid >> 3;
    const int ldch  = tid & 7;

    auto load_tile = [&](int buf, int k0) {
        const uint32_t a = sA0 + buf * ASZ;
        const uint32_t b = sB0 + buf * ASZ;
#pragma unroll
        for (int j = 0; j < 4; j++) {
            const int row = ldrow + j * 32;
            CP_ASYNC16(a + row * ROWB + ldch * 16,
                       Ag + (size_t)row * KTP + k0 + ldch * 8);
        }
#pragma unroll
        for (int j = 0; j < 4; j++) {
            const int row = ldrow + j * 32;
            CP_ASYNC16(b + row * ROWB + ldch * 16,
                       Bg + (size_t)row * KTP + k0 + ldch * 8);
        }
        CP_COMMIT();
    };

    float acc[2][8][4];
#pragma unroll
    for (int i = 0; i < 2; i++)
#pragma unroll
        for (int j = 0; j < 8; j++)
#pragma unroll
            for (int q = 0; q < 4; q++) acc[i][j][q] = 0.f;

    const int mbase = (wid >> 1) * 32;
    const int nbase = (wid & 1) * 64;

    const int a_row = (lane & 15);
    const int a_off = (lane >> 4) * 16;
    const int b_row = ((lane >> 4) << 3) + (lane & 7);
    const int b_off = ((lane >> 3) & 1) * 16;

    load_tile(0, 0);
    load_tile(1, BK);

#pragma unroll 1
    for (int it = 0; it < GITER; it++) {
        const int buf = it % NSTAGE;
        CP_WAIT(1);
        __syncthreads();
        if (it + 2 < GITER) load_tile((it + 2) % NSTAGE, (it + 2) * BK);

        const uint32_t sAb = sA0 + buf * ASZ;
        const uint32_t sBb = sB0 + buf * ASZ;
#pragma unroll
        for (int k16 = 0; k16 < 4; k16++) {
            uint32_t a[2][4];
#pragma unroll
            for (int i = 0; i < 2; i++) {
                const uint32_t addr = sAb
                    + (mbase + i * 16 + a_row) * ROWB + k16 * 32 + a_off;
                LDMATRIX_X4(a[i][0], a[i][1], a[i][2], a[i][3], addr);
            }
            uint32_t b[4][4];
#pragma unroll
            for (int g = 0; g < 4; g++) {
                const uint32_t addr = sBb
                    + (nbase + g * 16 + b_row) * ROWB + k16 * 32 + b_off;
                LDMATRIX_X4(b[g][0], b[g][1], b[g][2], b[g][3], addr);
            }
#pragma unroll
            for (int i = 0; i < 2; i++)
#pragma unroll
                for (int g = 0; g < 4; g++) {
                    MMA16816F(acc[i][2 * g],     a[i], (&b[g][0]));
                    MMA16816F(acc[i][2 * g + 1], a[i], (&b[g][2]));
                }
        }
    }

    const int head = nblk * 2 + (wid & 1);
    const float* nw = (z ? vw : qw) + head * HD;
    float* Out = (z ? g_V : g_Q);

    float nwv[8][2];
#pragma unroll
    for (int j = 0; j < 8; j++) {
        float2 t = *(const float2*)(nw + j * 8 + 2 * (lane & 3));
        nwv[j][0] = t.x; nwv[j][1] = t.y;
    }

#pragma unroll
    for (int i = 0; i < 2; i++) {
#pragma unroll
        for (int hh = 0; hh < 2; hh++) {
            float ss = 0.f;
#pragma unroll
            for (int j = 0; j < 8; j++) {
                const float v0 = acc[i][j][2 * hh];
                const float v1 = acc[i][j][2 * hh + 1];
                ss = fmaf(v0, v0, fmaf(v1, v1, ss));
            }
            ss += __shfl_xor_sync(0xffffffffu, ss, 1);
            ss += __shfl_xor_sync(0xffffffffu, ss, 2);
            const float inv = rsqrtf(ss * (1.0f / 64.0f) + 1e-8f);

            const int row = mblk * BM + mbase + i * 16 + hh * 8 + (lane >> 2);
            float* op = Out + (size_t)row * DD + head * HD + 2 * (lane & 3);
#pragma unroll
            for (int j = 0; j < 8; j++) {
                float2 o;
                o.x = acc[i][j][2 * hh]     * inv * nwv[j][0];
                o.y = acc[i][j][2 * hh + 1] * inv * nwv[j][1];
                *(float2*)(op + j * 8) = o;
            }
        }
    }
}

// ---------------------------------------------------------------------------
// Kernel B (HMMA): per-chunk S^T[e][d] = sum_t V[t][e] * K[t][d].
// A = V^T (rows e), B = K^T (rows d), bf16x3. 128 threads, 4 warps (16 rows ea).
// ---------------------------------------------------------------------------
__global__ __launch_bounds__(128) void k_chunk_kv(const float* __restrict__ X)
{
    extern __shared__ char sm[];
    const int c = blockIdx.x, h = blockIdx.y, b = blockIdx.z;
    const int tid = threadIdx.x, wid = tid >> 5, lane = tid & 31;

    char* VThi = sm;            // 8KB each
    char* VTlo = sm + 8192;
    char* KThi = sm + 16384;
    char* KTlo = sm + 24576;

    const float* Kg = X   + ((size_t)(b * LL + c * CH)) * DD + h * HD;
    const float* Vg = g_V + ((size_t)(b * LL + c * CH)) * DD + h * HD;

    conv_tr64(Vg, DD, VThi, VTlo, tid);
    conv_tr64(Kg, DD, KThi, KTlo, tid);
    __syncthreads();

    const uint32_t uVThi = s2u(VThi), uVTlo = s2u(VTlo);
    const uint32_t uKThi = s2u(KThi), uKTlo = s2u(KTlo);
    const int mbase = wid * 16;
    const int arow = mbase + (lane & 15);

    float acc[8][4];
#pragma unroll
    for (int j = 0; j < 8; j++)
#pragma unroll
        for (int q = 0; q < 4; q++) acc[j][q] = 0.f;

#pragma unroll
    for (int s = 0; s < 3; s++) {
        const uint32_t Ab = (s == 1) ? uVTlo : uVThi;   // A pattern [hi|lo|hi]
        const uint32_t Bb = (s == 2) ? uKTlo : uKThi;   // B pattern [hi|hi|lo]
#pragma unroll
        for (int k16 = 0; k16 < 4; k16++) {
            uint32_t a[4];
            LDMATRIX_X4(a[0], a[1], a[2], a[3],
                Ab + arow * 128 + (((2 * k16 + (lane >> 4)) ^ (lane & 7)) << 4));
#pragma unroll
            for (int g = 0; g < 4; g++) {
                const int grow = g * 16 + ((lane >> 4) << 3) + (lane & 7);
                uint32_t bb[4];
                LDMATRIX_X4(bb[0], bb[1], bb[2], bb[3],
                    Bb + grow * 128
                    + (((2 * k16 + ((lane >> 3) & 1)) ^ (lane & 7)) << 4));
                MMA16816(acc[2 * g],     a, bb);
                MMA16816(acc[2 * g + 1], a, (bb + 2));
            }
        }
    }

    float* Sp = g_S + (size_t)((b * HH + h) * NC + c) * (HD * HD);
#pragma unroll
    for (int j = 0; j < 8; j++)
#pragma unroll
        for (int hh = 0; hh < 2; hh++) {
            const int e = mbase + (lane >> 2) + 8 * hh;
            const int d = 8 * j + 2 * (lane & 3);
            float2 o = {acc[j][2 * hh], acc[j][2 * hh + 1]};
            *(float2*)(Sp + e * HD + d) = o;
        }
}

// ---------------------------------------------------------------------------
// Kernel C: EXCLUSIVE prefix sum over 16 chunks (float4 per thread).
// Grid (32 bh, 4); 256 threads; each thread owns one float4 across chunks.
// ---------------------------------------------------------------------------
__global__ __launch_bounds__(256) void k_prefix()
{
    const int bh = blockIdx.x;
    const int e4 = blockIdx.y * 256 + threadIdx.x;   // 0..1023
    float4* base = (float4*)(g_S + (size_t)bh * NC * HD * HD) + e4;
    float4 run = {0.f, 0.f, 0.f, 0.f};
#pragma unroll
    for (int c = 0; c < NC; c++) {
        float4 v = base[c * (HD * HD / 4)];
        base[c * (HD * HD / 4)] = run;
        run.x += v.x; run.y += v.y; run.z += v.z; run.w += v.w;
    }
}

// ---------------------------------------------------------------------------
// Kernel D (HMMA): per-chunk output. 128 threads, 4 warps (16 rows each).
//   GEMM1: [O1 | A] = Q @ [S^T-rows | K]   (N=128, causal skip in A region)
//   mask A, re-split hi/lo, GEMM2: O = O1 + A @ V^T
// ---------------------------------------------------------------------------
__global__ __launch_bounds__(128) void k_out(const float* __restrict__ X,
                                             float* __restrict__ Out)
{
    extern __shared__ char sm[];
    const int c = blockIdx.x, h = blockIdx.y, b = blockIdx.z;
    const int tid = threadIdx.x, wid = tid >> 5, lane = tid & 31;

    char* Qhi = sm;             // 8KB
    char* Qlo = sm + 8192;
    char* B1hi = sm + 16384;    // 16KB : rows 0-63 = S^T, rows 64-127 = K
    char* B1lo = sm + 32768;
    char* A2hi = sm + 16384;    // phase-B aliases
    char* A2lo = sm + 24576;
    char* VThi = sm + 32768;
    char* VTlo = sm + 40960;

    const float* Qg = g_Q + ((size_t)(b * LL + c * CH)) * DD + h * HD;
    const float* Kg = X   + ((size_t)(b * LL + c * CH)) * DD + h * HD;
    const float* Vg = g_V + ((size_t)(b * LL + c * CH)) * DD + h * HD;
    const float* Sp = g_S + (size_t)((b * HH + h) * NC + c) * (HD * HD);

    conv_nat64(Qg, DD, Qhi, Qlo, 0, tid);
    conv_nat64(Sp, HD, B1hi, B1lo, 0, tid);
    conv_nat64(Kg, DD, B1hi, B1lo, 64, tid);
    __syncthreads();

    const uint32_t uQhi = s2u(Qhi), uQlo = s2u(Qlo);
    const uint32_t uB1hi = s2u(B1hi), uB1lo = s2u(B1lo);
    const int mbase = wid * 16;
    const int arow = mbase + (lane & 15);

    float acc[16][4];
#pragma unroll
    for (int j = 0; j < 16; j++)
#pragma unroll
        for (int q = 0; q < 4; q++) acc[j][q] = 0.f;

    // GEMM1
#pragma unroll
    for (int s = 0; s < 3; s++) {
        const uint32_t Ab = (s == 1) ? uQlo : uQhi;
        const uint32_t Bb = (s == 2) ? uB1lo : uB1hi;
#pragma unroll
        for (int k16 = 0; k16 < 4; k16++) {
            uint32_t a[4];
            LDMATRIX_X4(a[0], a[1], a[2], a[3],
                Ab + arow * 128 + (((2 * k16 + (lane >> 4)) ^ (lane & 7)) << 4));
#pragma unroll
            for (int g = 0; g < 8; g++) {
                if (g >= 4 && (g - 4) > wid) continue;  // fully-masked A tiles
                const int grow = g * 16 + ((lane >> 4) << 3) + (lane & 7);
                uint32_t bb[4];
                LDMATRIX_X4(bb[0], bb[1], bb[2], bb[3],
                    Bb + grow * 128
                    + (((2 * k16 + ((lane >> 3) & 1)) ^ (lane & 7)) << 4));
                MMA16816(acc[2 * g],     a, bb);
                MMA16816(acc[2 * g + 1], a, (bb + 2));
            }
        }
    }

    __syncthreads();   // B1 reads complete; safe to overwrite with A2/VT

    // Causal mask + re-split A into smem
#pragma unroll
    for (int j = 8; j < 16; j++)
#pragma unroll
        for (int q = 0; q < 4; q++) {
            const int t = (j - 8) * 8 + 2 * (lane & 3) + (q & 1);
            const int l = mbase + (lane >> 2) + 8 * (q >> 1);
            const float v = (t <= l) ? acc[j][q] : 0.f;
            const __nv_bfloat16 hi = __float2bfloat16(v);
            const __nv_bfloat16 lo =
                __float2bfloat16(v - __bfloat162float(hi));
            const int off = l * 128 + (((t >> 3) ^ (l & 7)) << 4) + (t & 7) * 2;
            *(__nv_bfloat16*)(A2hi + off) = hi;
            *(__nv_bfloat16*)(A2lo + off) = lo;
        }

    conv_tr64(Vg, DD, VThi, VTlo, tid);
    __syncthreads();

    const uint32_t uA2hi = s2u(A2hi), uA2lo = s2u(A2lo);
    const uint32_t uVThi = s2u(VThi), uVTlo = s2u(VTlo);

    // GEMM2: O(acc[0..7]) += A @ V^T
#pragma unroll
    for (int s = 0; s < 3; s++) {
        const uint32_t Ab = (s == 1) ? uA2lo : uA2hi;
        const uint32_t Bb = (s == 2) ? uVTlo : uVThi;
#pragma unroll
        for (int k16 = 0; k16 < 4; k16++) {
            uint32_t a[4];
            LDMATRIX_X4(a[0], a[1], a[2], a[3],
                Ab + arow * 128 + (((2 * k16 + (lane >> 4)) ^ (lane & 7)) << 4));
#pragma unroll
            for (int g = 0; g < 4; g++) {
                const int grow = g * 16 + ((lane >> 4) << 3) + (lane & 7);
                uint32_t bb[4];
                LDMATRIX_X4(bb[0], bb[1], bb[2], bb[3],
                    Bb + grow * 128
                    + (((2 * k16 + ((lane >> 3) & 1)) ^ (lane & 7)) << 4));
                MMA16816(acc[2 * g],     a, bb);
                MMA16816(acc[2 * g + 1], a, (bb + 2));
            }
        }
    }

    // Write O
    float* Op = Out + ((size_t)(b * LL + c * CH)) * DD + h * HD;
#pragma unroll
    for (int j = 0; j < 8; j++)
#pragma unroll
        for (int hh = 0; hh < 2; hh++) {
            const int l = mbase + (lane >> 2) + 8 * hh;
            const int e = 8 * j + 2 * (lane & 3);
            float2 o = {acc[j][2 * hh], acc[j][2 * hh + 1]};
            *(float2*)(Op + (size_t)l * DD + e) = o;
        }
}

// ---------------------------------------------------------------------------
extern "C" void kernel_launch(void* const* d_in, const int* in_sizes, int n_in,
                              void* d_out, int out_size)
{
    const float* X  = (const float*)d_in[0];
    const float* Wq = (const float*)d_in[1];
    const float* Wv = (const float*)d_in[2];
    const float* qw = (const float*)d_in[3];
    const float* vw = (const float*)d_in[4];
    float* Out = (float*)d_out;

    const int SMEM_PROJ = 2 * NSTAGE * ASZ;  // 110592 bytes
    cudaFuncSetAttribute(k_proj, cudaFuncAttributeMaxDynamicSharedMemorySize,
                         SMEM_PROJ);
    cudaFuncSetAttribute(k_out, cudaFuncAttributeMaxDynamicSharedMemorySize,
                         49152);
    cudaFuncSetAttribute(k_chunk_kv,
                         cudaFuncAttributeMaxDynamicSharedMemorySize, 32768);

    k_split   <<<dim3(1024, 1, 3), 256>>>(X, Wq, Wv);
    k_proj    <<<dim3(16, 8, 2), 256, SMEM_PROJ>>>(qw, vw);
    k_chunk_kv<<<dim3(16, 16, 2), 128, 32768>>>(X);
    k_prefix  <<<dim3(32, 4), 256>>>();
    k_out     <<<dim3(16, 16, 2), 128, 49152>>>(X, Out);
}

// round 8
// speedup vs baseline: 4.2478x; 1.3797x over previous
#include <cuda_runtime.h>
#include <cuda_bf16.h>
#include <cuda_fp16.h>
#include <cstdint>
#include <cstring>

// Problem constants (fixed shapes from reference)
#define BB   2
#define LL   1024
#define DD   1024
#define HH   16
#define HD   64      // head dim
#define NC   16      // number of chunks per sequence
#define CH   64      // chunk length
#define MTOT (BB*LL) // 2048 rows

// Projection GEMM: plain fp16, K = 1024.
// Dropped terms eA.B + A.eB ~ 2^-12 each (independent) => ~4.2e-4 end-to-end.
#define KTP  1024
#define BK   64
#define GITER (KTP/BK)    // 16
#define BM   128
#define BN   128
#define ROWB 144          // padded smem row stride in bytes (64 x 2B + 16 pad)
#define ASZ  (128*ROWB)   // 18432 bytes per tile buffer
#define NSTAGE 3

// Scratch (no allocations allowed in kernel_launch)
__device__ float g_Q[MTOT * DD];                 // 8 MB : normalized Q
__device__ float g_V[MTOT * DD];                 // 8 MB : normalized V
__device__ float g_S[BB * HH * NC * HD * HD];    // 8 MB : per-chunk S^T sums
__device__ __half g_Ax [MTOT * KTP];             // 4 MB : X (fp16)
__device__ __half g_Wq2[DD * KTP];               // 2 MB : Wq (fp16)
__device__ __half g_Wv2[DD * KTP];               // 2 MB : Wv (fp16)

static __device__ __forceinline__ uint32_t s2u(const void* p) {
    uint32_t a;
    asm("{ .reg .u64 t; cvta.to.shared.u64 t, %1; cvt.u32.u64 %0, t; }"
        : "=r"(a) : "l"(p));
    return a;
}
static __device__ __forceinline__ uint32_t b2u(__nv_bfloat162 v) {
    uint32_t u; memcpy(&u, &v, 4); return u;
}
static __device__ __forceinline__ uint32_t h2u(__half2 v) {
    uint32_t u; memcpy(&u, &v, 4); return u;
}

#define CP_ASYNC16(saddr, gptr) \
    asm volatile("cp.async.cg.shared.global [%0], [%1], 16;" \
                 :: "r"(saddr), "l"(gptr))
#define CP_COMMIT() asm volatile("cp.async.commit_group;")
#define CP_WAIT(n)  asm volatile("cp.async.wait_group %0;" :: "n"(n))

#define LDMATRIX_X4(r0, r1, r2, r3, addr) \
    asm volatile("ldmatrix.sync.aligned.m8n8.x4.shared.b16 {%0,%1,%2,%3}, [%4];" \
                 : "=r"(r0), "=r"(r1), "=r"(r2), "=r"(r3) : "r"(addr))

// bf16 MMA (attention kernels)
#define MMA16816(d, a, b) \
    asm volatile("mma.sync.aligned.m16n8k16.row.col.f32.bf16.bf16.f32 " \
                 "{%0,%1,%2,%3}, {%4,%5,%6,%7}, {%8,%9}, {%0,%1,%2,%3};" \
                 : "+f"((d)[0]), "+f"((d)[1]), "+f"((d)[2]), "+f"((d)[3]) \
                 : "r"((a)[0]), "r"((a)[1]), "r"((a)[2]), "r"((a)[3]),   \
                   "r"((b)[0]), "r"((b)[1]))

// fp16 MMA (projection)
#define MMA16816F(d, a, b) \
    asm volatile("mma.sync.aligned.m16n8k16.row.col.f32.f16.f16.f32 " \
                 "{%0,%1,%2,%3}, {%4,%5,%6,%7}, {%8,%9}, {%0,%1,%2,%3};" \
                 : "+f"((d)[0]), "+f"((d)[1]), "+f"((d)[2]), "+f"((d)[3]) \
                 : "r"((a)[0]), "r"((a)[1]), "r"((a)[2]), "r"((a)[3]),   \
                   "r"((b)[0]), "r"((b)[1]))

// ---------------------------------------------------------------------------
// fp32 64x64 -> bf16 hi/lo into XOR-swizzled smem (128B rows, chunk^(row&7)).
// natural: dst row = src row (+rowoff), dst col = src col.
// ---------------------------------------------------------------------------
static __device__ __forceinline__ void conv_nat64(
    const float* __restrict__ src, int stride, char* dhi, char* dlo,
    int rowoff, int tid)
{
#pragma unroll
    for (int p = 0; p < 8; p++) {
        const int f = tid + p * 128;
        const int r = f >> 4, cc = (f & 15) * 4;
        float4 v = *(const float4*)(src + (size_t)r * stride + cc);
        float vs[4] = {v.x, v.y, v.z, v.w};
        __nv_bfloat16 h[4], l[4];
#pragma unroll
        for (int i = 0; i < 4; i++) {
            h[i] = __float2bfloat16(vs[i]);
            l[i] = __float2bfloat16(vs[i] - __bfloat162float(h[i]));
        }
        uint2 H = { b2u(__halves2bfloat162(h[0], h[1])),
                    b2u(__halves2bfloat162(h[2], h[3])) };
        uint2 L = { b2u(__halves2bfloat162(l[0], l[1])),
                    b2u(__halves2bfloat162(l[2], l[3])) };
        const int row = r + rowoff;
        const int off = row * 128 + (((cc >> 3) ^ (row & 7)) << 4) + (cc & 7) * 2;
        *(uint2*)(dhi + off) = H;
        *(uint2*)(dlo + off) = L;
    }
}

// transposed: dst row = src col, dst col = src row.
static __device__ __forceinline__ void conv_tr64(
    const float* __restrict__ src, int stride, char* dhi, char* dlo, int tid)
{
#pragma unroll
    for (int p = 0; p < 8; p++) {
        const int f = tid + p * 128;
        const int r = f >> 4, cc = (f & 15) * 4;
        float4 v = *(const float4*)(src + (size_t)r * stride + cc);
        float vs[4] = {v.x, v.y, v.z, v.w};
#pragma unroll
        for (int i = 0; i < 4; i++) {
            __nv_bfloat16 hi = __float2bfloat16(vs[i]);
            __nv_bfloat16 lo = __float2bfloat16(vs[i] - __bfloat162float(hi));
            const int row = cc + i, col = r;
            const int off = row * 128 + (((col >> 3) ^ (row & 7)) << 4)
                          + (col & 7) * 2;
            *(__nv_bfloat16*)(dhi + off) = hi;
            *(__nv_bfloat16*)(dlo + off) = lo;
        }
    }
}

// ---------------------------------------------------------------------------
// Kernel S: fp32 -> fp16.  8 elements/thread, one 16B store.
// z=0: X -> g_Ax;  z=1: Wq -> g_Wq2;  z=2: Wv -> g_Wv2.
// ---------------------------------------------------------------------------
__global__ __launch_bounds__(256) void k_split(
    const float* __restrict__ X, const float* __restrict__ Wq,
    const float* __restrict__ Wv)
{
    const int z = blockIdx.z;
    const float* src = (z == 0) ? X : (z == 1) ? Wq : Wv;
    __half* dst = (z == 0) ? g_Ax : (z == 1) ? g_Wq2 : g_Wv2;
    const int rows = (z == 0) ? MTOT : DD;

    const int gid = blockIdx.x * 256 + threadIdx.x;
    const int idx8 = gid * 8;
    if (idx8 >= rows * DD) return;

    const float* sp = src + (size_t)idx8;
    float4 v0 = *(const float4*)(sp);
    float4 v1 = *(const float4*)(sp + 4);
    float vs[8] = {v0.x, v0.y, v0.z, v0.w, v1.x, v1.y, v1.z, v1.w};
    __half h[8];
#pragma unroll
    for (int i = 0; i < 8; i++) h[i] = __float2half_rn(vs[i]);
    uint4 HU;
    HU.x = h2u(__halves2half2(h[0], h[1]));
    HU.y = h2u(__halves2half2(h[2], h[3]));
    HU.z = h2u(__halves2half2(h[4], h[5]));
    HU.w = h2u(__halves2half2(h[6], h[7]));
    *(uint4*)(dst + (size_t)idx8) = HU;
}

// ---------------------------------------------------------------------------
// Kernel P: projection GEMM via fp16 mma.sync + fused per-head RMSNorm.
// K=1024, 3-stage cp.async pipeline; grid (16 m, 8 n, 2 {Q,V}); 8 warps.
// ---------------------------------------------------------------------------
__global__ __launch_bounds__(256, 2) void k_proj(
    const float* __restrict__ qw, const float* __restrict__ vw)
{
    extern __shared__ char smem[];
    const int tid = threadIdx.x, wid = tid >> 5, lane = tid & 31;
    const int mblk = blockIdx.x, nblk = blockIdx.y, z = blockIdx.z;

    const uint32_t sA0 = s2u(smem);
    const uint32_t sB0 = sA0 + NSTAGE * ASZ;

    const __half* Ag = g_Ax + (size_t)mblk * BM * KTP;
    const __half* Bg = (z ? g_Wv2 : g_Wq2) + (size_t)nblk * BN * KTP;

    const int ldrow = tid >> 3;
    const int ldch  = tid & 7;

    auto load_tile = [&](int buf, int k0) {
        const uint32_t a = sA0 + buf * ASZ;
        const uint32_t b = sB0 + buf * ASZ;
#pragma unroll
        for (int j = 0; j < 4; j++) {
            const int row = ldrow + j * 32;
            CP_ASYNC16(a + row * ROWB + ldch * 16,
                       Ag + (size_t)row * KTP + k0 + ldch * 8);
        }
#pragma unroll
        for (int j = 0; j < 4; j++) {
            const int row = ldrow + j * 32;
            CP_ASYNC16(b + row * ROWB + ldch * 16,
                       Bg + (size_t)row * KTP + k0 + ldch * 8);
        }
        CP_COMMIT();
    };

    float acc[2][8][4];
#pragma unroll
    for (int i = 0; i < 2; i++)
#pragma unroll
        for (int j = 0; j < 8; j++)
#pragma unroll
            for (int q = 0; q < 4; q++) acc[i][j][q] = 0.f;

    const int mbase = (wid >> 1) * 32;
    const int nbase = (wid & 1) * 64;

    const int a_row = (lane & 15);
    const int a_off = (lane >> 4) * 16;
    const int b_row = ((lane >> 4) << 3) + (lane & 7);
    const int b_off = ((lane >> 3) & 1) * 16;

    load_tile(0, 0);
    load_tile(1, BK);

#pragma unroll 1
    for (int it = 0; it < GITER; it++) {
        const int buf = it % NSTAGE;
        CP_WAIT(1);
        __syncthreads();
        if (it + 2 < GITER) load_tile((it + 2) % NSTAGE, (it + 2) * BK);

        const uint32_t sAb = sA0 + buf * ASZ;
        const uint32_t sBb = sB0 + buf * ASZ;
#pragma unroll
        for (int k16 = 0; k16 < 4; k16++) {
            uint32_t a[2][4];
#pragma unroll
            for (int i = 0; i < 2; i++) {
                const uint32_t addr = sAb
                    + (mbase + i * 16 + a_row) * ROWB + k16 * 32 + a_off;
                LDMATRIX_X4(a[i][0], a[i][1], a[i][2], a[i][3], addr);
            }
            uint32_t b[4][4];
#pragma unroll
            for (int g = 0; g < 4; g++) {
                const uint32_t addr = sBb
                    + (nbase + g * 16 + b_row) * ROWB + k16 * 32 + b_off;
                LDMATRIX_X4(b[g][0], b[g][1], b[g][2], b[g][3], addr);
            }
#pragma unroll
            for (int i = 0; i < 2; i++)
#pragma unroll
                for (int g = 0; g < 4; g++) {
                    MMA16816F(acc[i][2 * g],     a[i], (&b[g][0]));
                    MMA16816F(acc[i][2 * g + 1], a[i], (&b[g][2]));
                }
        }
    }

    const int head = nblk * 2 + (wid & 1);
    const float* nw = (z ? vw : qw) + head * HD;
    float* Out = (z ? g_V : g_Q);

    float nwv[8][2];
#pragma unroll
    for (int j = 0; j < 8; j++) {
        float2 t = *(const float2*)(nw + j * 8 + 2 * (lane & 3));
        nwv[j][0] = t.x; nwv[j][1] = t.y;
    }

#pragma unroll
    for (int i = 0; i < 2; i++) {
#pragma unroll
        for (int hh = 0; hh < 2; hh++) {
            float ss = 0.f;
#pragma unroll
            for (int j = 0; j < 8; j++) {
                const float v0 = acc[i][j][2 * hh];
                const float v1 = acc[i][j][2 * hh + 1];
                ss = fmaf(v0, v0, fmaf(v1, v1, ss));
            }
            ss += __shfl_xor_sync(0xffffffffu, ss, 1);
            ss += __shfl_xor_sync(0xffffffffu, ss, 2);
            const float inv = rsqrtf(ss * (1.0f / 64.0f) + 1e-8f);

            const int row = mblk * BM + mbase + i * 16 + hh * 8 + (lane >> 2);
            float* op = Out + (size_t)row * DD + head * HD + 2 * (lane & 3);
#pragma unroll
            for (int j = 0; j < 8; j++) {
                float2 o;
                o.x = acc[i][j][2 * hh]     * inv * nwv[j][0];
                o.y = acc[i][j][2 * hh + 1] * inv * nwv[j][1];
                *(float2*)(op + j * 8) = o;
            }
        }
    }
}

// ---------------------------------------------------------------------------
// Kernel B (HMMA): per-chunk S^T[e][d] = sum_t V[t][e] * K[t][d].
// A = V^T (rows e), B = K^T (rows d), bf16x3. 128 threads, 4 warps (16 rows ea).
// ---------------------------------------------------------------------------
__global__ __launch_bounds__(128) void k_chunk_kv(const float* __restrict__ X)
{
    extern __shared__ char sm[];
    const int c = blockIdx.x, h = blockIdx.y, b = blockIdx.z;
    const int tid = threadIdx.x, wid = tid >> 5, lane = tid & 31;

    char* VThi = sm;            // 8KB each
    char* VTlo = sm + 8192;
    char* KThi = sm + 16384;
    char* KTlo = sm + 24576;

    const float* Kg = X   + ((size_t)(b * LL + c * CH)) * DD + h * HD;
    const float* Vg = g_V + ((size_t)(b * LL + c * CH)) * DD + h * HD;

    conv_tr64(Vg, DD, VThi, VTlo, tid);
    conv_tr64(Kg, DD, KThi, KTlo, tid);
    __syncthreads();

    const uint32_t uVThi = s2u(VThi), uVTlo = s2u(VTlo);
    const uint32_t uKThi = s2u(KThi), uKTlo = s2u(KTlo);
    const int mbase = wid * 16;
    const int arow = mbase + (lane & 15);

    float acc[8][4];
#pragma unroll
    for (int j = 0; j < 8; j++)
#pragma unroll
        for (int q = 0; q < 4; q++) acc[j][q] = 0.f;

#pragma unroll
    for (int s = 0; s < 3; s++) {
        const uint32_t Ab = (s == 1) ? uVTlo : uVThi;   // A pattern [hi|lo|hi]
        const uint32_t Bb = (s == 2) ? uKTlo : uKThi;   // B pattern [hi|hi|lo]
#pragma unroll
        for (int k16 = 0; k16 < 4; k16++) {
            uint32_t a[4];
            LDMATRIX_X4(a[0], a[1], a[2], a[3],
                Ab + arow * 128 + (((2 * k16 + (lane >> 4)) ^ (lane & 7)) << 4));
#pragma unroll
            for (int g = 0; g < 4; g++) {
                const int grow = g * 16 + ((lane >> 4) << 3) + (lane & 7);
                uint32_t bb[4];
                LDMATRIX_X4(bb[0], bb[1], bb[2], bb[3],
                    Bb + grow * 128
                    + (((2 * k16 + ((lane >> 3) & 1)) ^ (lane & 7)) << 4));
                MMA16816(acc[2 * g],     a, bb);
                MMA16816(acc[2 * g + 1], a, (bb + 2));
            }
        }
    }

    float* Sp = g_S + (size_t)((b * HH + h) * NC + c) * (HD * HD);
#pragma unroll
    for (int j = 0; j < 8; j++)
#pragma unroll
        for (int hh = 0; hh < 2; hh++) {
            const int e = mbase + (lane >> 2) + 8 * hh;
            const int d = 8 * j + 2 * (lane & 3);
            float2 o = {acc[j][2 * hh], acc[j][2 * hh + 1]};
            *(float2*)(Sp + e * HD + d) = o;
        }
}

// ---------------------------------------------------------------------------
// Kernel C: EXCLUSIVE prefix sum over 16 chunks. Grid (32 bh, 16); scalar
// element per thread; all 16 loads issued before any store (MLP=16).
// ---------------------------------------------------------------------------
__global__ __launch_bounds__(256) void k_prefix()
{
    const int bh = blockIdx.x;
    const int e = blockIdx.y * 256 + threadIdx.x;
    float* base = g_S + (size_t)bh * NC * HD * HD + e;
    float v[NC];
#pragma unroll
    for (int c = 0; c < NC; c++) v[c] = base[c * (HD * HD)];
    float run = 0.f;
#pragma unroll
    for (int c = 0; c < NC; c++) {
        base[c * (HD * HD)] = run;
        run += v[c];
    }
}

// ---------------------------------------------------------------------------
// Kernel D (HMMA): per-chunk output. 128 threads, 4 warps (16 rows each).
//   GEMM1: [O1 | A] = Q @ [S^T-rows | K]   (N=128, causal skip in A region)
//   mask A, re-split hi/lo, GEMM2: O = O1 + A @ V^T
// ---------------------------------------------------------------------------
__global__ __launch_bounds__(128) void k_out(const float* __restrict__ X,
                                             float* __restrict__ Out)
{
    extern __shared__ char sm[];
    const int c = blockIdx.x, h = blockIdx.y, b = blockIdx.z;
    const int tid = threadIdx.x, wid = tid >> 5, lane = tid & 31;

    char* Qhi = sm;             // 8KB
    char* Qlo = sm + 8192;
    char* B1hi = sm + 16384;    // 16KB : rows 0-63 = S^T, rows 64-127 = K
    char* B1lo = sm + 32768;
    char* A2hi = sm + 16384;    // phase-B aliases
    char* A2lo = sm + 24576;
    char* VThi = sm + 32768;
    char* VTlo = sm + 40960;

    const float* Qg = g_Q + ((size_t)(b * LL + c * CH)) * DD + h * HD;
    const float* Kg = X   + ((size_t)(b * LL + c * CH)) * DD + h * HD;
    const float* Vg = g_V + ((size_t)(b * LL + c * CH)) * DD + h * HD;
    const float* Sp = g_S + (size_t)((b * HH + h) * NC + c) * (HD * HD);

    conv_nat64(Qg, DD, Qhi, Qlo, 0, tid);
    conv_nat64(Sp, HD, B1hi, B1lo, 0, tid);
    conv_nat64(Kg, DD, B1hi, B1lo, 64, tid);
    __syncthreads();

    const uint32_t uQhi = s2u(Qhi), uQlo = s2u(Qlo);
    const uint32_t uB1hi = s2u(B1hi), uB1lo = s2u(B1lo);
    const int mbase = wid * 16;
    const int arow = mbase + (lane & 15);

    float acc[16][4];
#pragma unroll
    for (int j = 0; j < 16; j++)
#pragma unroll
        for (int q = 0; q < 4; q++) acc[j][q] = 0.f;

    // GEMM1
#pragma unroll
    for (int s = 0; s < 3; s++) {
        const uint32_t Ab = (s == 1) ? uQlo : uQhi;
        const uint32_t Bb = (s == 2) ? uB1lo : uB1hi;
#pragma unroll
        for (int k16 = 0; k16 < 4; k16++) {
            uint32_t a[4];
            LDMATRIX_X4(a[0], a[1], a[2], a[3],
                Ab + arow * 128 + (((2 * k16 + (lane >> 4)) ^ (lane & 7)) << 4));
#pragma unroll
            for (int g = 0; g < 8; g++) {
                if (g >= 4 && (g - 4) > wid) continue;  // fully-masked A tiles
                const int grow = g * 16 + ((lane >> 4) << 3) + (lane & 7);
                uint32_t bb[4];
                LDMATRIX_X4(bb[0], bb[1], bb[2], bb[3],
                    Bb + grow * 128
                    + (((2 * k16 + ((lane >> 3) & 1)) ^ (lane & 7)) << 4));
                MMA16816(acc[2 * g],     a, bb);
                MMA16816(acc[2 * g + 1], a, (bb + 2));
            }
        }
    }

    __syncthreads();   // B1 reads complete; safe to overwrite with A2/VT

    // Causal mask + re-split A into smem
#pragma unroll
    for (int j = 8; j < 16; j++)
#pragma unroll
        for (int q = 0; q < 4; q++) {
            const int t = (j - 8) * 8 + 2 * (lane & 3) + (q & 1);
            const int l = mbase + (lane >> 2) + 8 * (q >> 1);
            const float v = (t <= l) ? acc[j][q] : 0.f;
            const __nv_bfloat16 hi = __float2bfloat16(v);
            const __nv_bfloat16 lo =
                __float2bfloat16(v - __bfloat162float(hi));
            const int off = l * 128 + (((t >> 3) ^ (l & 7)) << 4) + (t & 7) * 2;
            *(__nv_bfloat16*)(A2hi + off) = hi;
            *(__nv_bfloat16*)(A2lo + off) = lo;
        }

    conv_tr64(Vg, DD, VThi, VTlo, tid);
    __syncthreads();

    const uint32_t uA2hi = s2u(A2hi), uA2lo = s2u(A2lo);
    const uint32_t uVThi = s2u(VThi), uVTlo = s2u(VTlo);

    // GEMM2: O(acc[0..7]) += A @ V^T
#pragma unroll
    for (int s = 0; s < 3; s++) {
        const uint32_t Ab = (s == 1) ? uA2lo : uA2hi;
        const uint32_t Bb = (s == 2) ? uVTlo : uVThi;
#pragma unroll
        for (int k16 = 0; k16 < 4; k16++) {
            uint32_t a[4];
            LDMATRIX_X4(a[0], a[1], a[2], a[3],
                Ab + arow * 128 + (((2 * k16 + (lane >> 4)) ^ (lane & 7)) << 4));
#pragma unroll
            for (int g = 0; g < 4; g++) {
                const int grow = g * 16 + ((lane >> 4) << 3) + (lane & 7);
                uint32_t bb[4];
                LDMATRIX_X4(bb[0], bb[1], bb[2], bb[3],
                    Bb + grow * 128
                    + (((2 * k16 + ((lane >> 3) & 1)) ^ (lane & 7)) << 4));
                MMA16816(acc[2 * g],     a, bb);
                MMA16816(acc[2 * g + 1], a, (bb + 2));
            }
        }
    }

    // Write O
    float* Op = Out + ((size_t)(b * LL + c * CH)) * DD + h * HD;
#pragma unroll
    for (int j = 0; j < 8; j++)
#pragma unroll
        for (int hh = 0; hh < 2; hh++) {
            const int l = mbase + (lane >> 2) + 8 * hh;
            const int e = 8 * j + 2 * (lane & 3);
            float2 o = {acc[j][2 * hh], acc[j][2 * hh + 1]};
            *(float2*)(Op + (size_t)l * DD + e) = o;
        }
}

// ---------------------------------------------------------------------------
extern "C" void kernel_launch(void* const* d_in, const int* in_sizes, int n_in,
                              void* d_out, int out_size)
{
    const float* X  = (const float*)d_in[0];
    const float* Wq = (const float*)d_in[1];
    const float* Wv = (const float*)d_in[2];
    const float* qw = (const float*)d_in[3];
    const float* vw = (const float*)d_in[4];
    float* Out = (float*)d_out;

    const int SMEM_PROJ = 2 * NSTAGE * ASZ;  // 110592 bytes
    cudaFuncSetAttribute(k_proj, cudaFuncAttributeMaxDynamicSharedMemorySize,
                         SMEM_PROJ);
    cudaFuncSetAttribute(k_out, cudaFuncAttributeMaxDynamicSharedMemorySize,
                         49152);
    cudaFuncSetAttribute(k_chunk_kv,
                         cudaFuncAttributeMaxDynamicSharedMemorySize, 32768);

    k_split   <<<dim3(1024, 1, 3), 256>>>(X, Wq, Wv);
    k_proj    <<<dim3(16, 8, 2), 256, SMEM_PROJ>>>(qw, vw);
    k_chunk_kv<<<dim3(16, 16, 2), 128, 32768>>>(X);
    k_prefix  <<<dim3(32, 16), 256>>>();
    k_out     <<<dim3(16, 16, 2), 128, 49152>>>(X, Out);
}

// round 9
// speedup vs baseline: 4.7316x; 1.1139x over previous
#include <cuda_runtime.h>
#include <cuda_bf16.h>
#include <cuda_fp16.h>
#include <cstdint>
#include <cstring>

// Problem constants (fixed shapes from reference)
#define BB   2
#define LL   1024
#define DD   1024
#define HH   16
#define HD   64      // head dim
#define NC   16      // number of chunks per sequence
#define CH   64      // chunk length
#define MTOT (BB*LL) // 2048 rows

// Projection GEMM: plain fp16, K = 1024.
#define KTP  1024
#define BK   64
#define GITER (KTP/BK)    // 16
#define BM   128
#define BN   128
#define ROWB 144          // padded smem row stride in bytes (64 x 2B + 16 pad)
#define ASZ  (128*ROWB)   // 18432 bytes per tile buffer
#define NSTAGE 3

// Scratch (no allocations allowed in kernel_launch)
__device__ float g_Q[MTOT * DD];                 // 8 MB : normalized Q
__device__ float g_V[MTOT * DD];                 // 8 MB : normalized V
__device__ float g_S[BB * HH * NC * HD * HD];    // 8 MB : per-chunk S^T sums
__device__ __half g_Ax [MTOT * KTP];             // 4 MB : X (fp16)
__device__ __half g_Wq2[DD * KTP];               // 2 MB : Wq (fp16)
__device__ __half g_Wv2[DD * KTP];               // 2 MB : Wv (fp16)

static __device__ __forceinline__ uint32_t s2u(const void* p) {
    uint32_t a;
    asm("{ .reg .u64 t; cvta.to.shared.u64 t, %1; cvt.u32.u64 %0, t; }"
        : "=r"(a) : "l"(p));
    return a;
}
static __device__ __forceinline__ uint32_t h2u(__half2 v) {
    uint32_t u; memcpy(&u, &v, 4); return u;
}

#define CP_ASYNC16(saddr, gptr) \
    asm volatile("cp.async.cg.shared.global [%0], [%1], 16;" \
                 :: "r"(saddr), "l"(gptr))
#define CP_COMMIT() asm volatile("cp.async.commit_group;")
#define CP_WAIT(n)  asm volatile("cp.async.wait_group %0;" :: "n"(n))

#define LDMATRIX_X4(r0, r1, r2, r3, addr) \
    asm volatile("ldmatrix.sync.aligned.m8n8.x4.shared.b16 {%0,%1,%2,%3}, [%4];" \
                 : "=r"(r0), "=r"(r1), "=r"(r2), "=r"(r3) : "r"(addr))

// fp16 MMA (all kernels)
#define MMA16816F(d, a, b) \
    asm volatile("mma.sync.aligned.m16n8k16.row.col.f32.f16.f16.f32 " \
                 "{%0,%1,%2,%3}, {%4,%5,%6,%7}, {%8,%9}, {%0,%1,%2,%3};" \
                 : "+f"((d)[0]), "+f"((d)[1]), "+f"((d)[2]), "+f"((d)[3]) \
                 : "r"((a)[0]), "r"((a)[1]), "r"((a)[2]), "r"((a)[3]),   \
                   "r"((b)[0]), "r"((b)[1]))

// ---------------------------------------------------------------------------
// fp32 64x64 -> fp16 into XOR-swizzled smem (128B rows, chunk^(row&7)).
// _h2: hi + lo (A operands, exact to 2^-22);  _h1: hi only (B operands).
// ---------------------------------------------------------------------------
static __device__ __forceinline__ void conv_nat64_h2(
    const float* __restrict__ src, int stride, char* dhi, char* dlo,
    int rowoff, int tid)
{
#pragma unroll
    for (int p = 0; p < 8; p++) {
        const int f = tid + p * 128;
        const int r = f >> 4, cc = (f & 15) * 4;
        float4 v = *(const float4*)(src + (size_t)r * stride + cc);
        float vs[4] = {v.x, v.y, v.z, v.w};
        __half h[4], l[4];
#pragma unroll
        for (int i = 0; i < 4; i++) {
            h[i] = __float2half_rn(vs[i]);
            l[i] = __float2half_rn(vs[i] - __half2float(h[i]));
        }
        uint2 H = { h2u(__halves2half2(h[0], h[1])),
                    h2u(__halves2half2(h[2], h[3])) };
        uint2 L = { h2u(__halves2half2(l[0], l[1])),
                    h2u(__halves2half2(l[2], l[3])) };
        const int row = r + rowoff;
        const int off = row * 128 + (((cc >> 3) ^ (row & 7)) << 4) + (cc & 7) * 2;
        *(uint2*)(dhi + off) = H;
        *(uint2*)(dlo + off) = L;
    }
}

static __device__ __forceinline__ void conv_nat64_h1(
    const float* __restrict__ src, int stride, char* dhi, int rowoff, int tid)
{
#pragma unroll
    for (int p = 0; p < 8; p++) {
        const int f = tid + p * 128;
        const int r = f >> 4, cc = (f & 15) * 4;
        float4 v = *(const float4*)(src + (size_t)r * stride + cc);
        uint2 H = { h2u(__halves2half2(__float2half_rn(v.x),
                                       __float2half_rn(v.y))),
                    h2u(__halves2half2(__float2half_rn(v.z),
                                       __float2half_rn(v.w))) };
        const int row = r + rowoff;
        const int off = row * 128 + (((cc >> 3) ^ (row & 7)) << 4) + (cc & 7) * 2;
        *(uint2*)(dhi + off) = H;
    }
}

// transposed variants: dst row = src col, dst col = src row.
static __device__ __forceinline__ void conv_tr64_h2(
    const float* __restrict__ src, int stride, char* dhi, char* dlo, int tid)
{
#pragma unroll
    for (int p = 0; p < 8; p++) {
        const int f = tid + p * 128;
        const int r = f >> 4, cc = (f & 15) * 4;
        float4 v = *(const float4*)(src + (size_t)r * stride + cc);
        float vs[4] = {v.x, v.y, v.z, v.w};
#pragma unroll
        for (int i = 0; i < 4; i++) {
            __half hi = __float2half_rn(vs[i]);
            __half lo = __float2half_rn(vs[i] - __half2float(hi));
            const int row = cc + i, col = r;
            const int off = row * 128 + (((col >> 3) ^ (row & 7)) << 4)
                          + (col & 7) * 2;
            *(__half*)(dhi + off) = hi;
            *(__half*)(dlo + off) = lo;
        }
    }
}

static __device__ __forceinline__ void conv_tr64_h1(
    const float* __restrict__ src, int stride, char* dhi, int tid)
{
#pragma unroll
    for (int p = 0; p < 8; p++) {
        const int f = tid + p * 128;
        const int r = f >> 4, cc = (f & 15) * 4;
        float4 v = *(const float4*)(src + (size_t)r * stride + cc);
        float vs[4] = {v.x, v.y, v.z, v.w};
#pragma unroll
        for (int i = 0; i < 4; i++) {
            const int row = cc + i, col = r;
            const int off = row * 128 + (((col >> 3) ^ (row & 7)) << 4)
                          + (col & 7) * 2;
            *(__half*)(dhi + off) = __float2half_rn(vs[i]);
        }
    }
}

// ---------------------------------------------------------------------------
// Kernel S: fp32 -> fp16.  8 elements/thread, one 16B store.
// ---------------------------------------------------------------------------
__global__ __launch_bounds__(256) void k_split(
    const float* __restrict__ X, const float* __restrict__ Wq,
    const float* __restrict__ Wv)
{
    const int z = blockIdx.z;
    const float* src = (z == 0) ? X : (z == 1) ? Wq : Wv;
    __half* dst = (z == 0) ? g_Ax : (z == 1) ? g_Wq2 : g_Wv2;
    const int rows = (z == 0) ? MTOT : DD;

    const int gid = blockIdx.x * 256 + threadIdx.x;
    const int idx8 = gid * 8;
    if (idx8 >= rows * DD) return;

    const float* sp = src + (size_t)idx8;
    float4 v0 = *(const float4*)(sp);
    float4 v1 = *(const float4*)(sp + 4);
    float vs[8] = {v0.x, v0.y, v0.z, v0.w, v1.x, v1.y, v1.z, v1.w};
    __half h[8];
#pragma unroll
    for (int i = 0; i < 8; i++) h[i] = __float2half_rn(vs[i]);
    uint4 HU;
    HU.x = h2u(__halves2half2(h[0], h[1]));
    HU.y = h2u(__halves2half2(h[2], h[3]));
    HU.z = h2u(__halves2half2(h[4], h[5]));
    HU.w = h2u(__halves2half2(h[6], h[7]));
    *(uint4*)(dst + (size_t)idx8) = HU;
}

// ---------------------------------------------------------------------------
// Kernel P: projection GEMM via fp16 mma.sync + fused per-head RMSNorm.
// K=1024, 3-stage cp.async pipeline; grid (16 m, 8 n, 2 {Q,V}); 8 warps.
// ---------------------------------------------------------------------------
__global__ __launch_bounds__(256, 2) void k_proj(
    const float* __restrict__ qw, const float* __restrict__ vw)
{
    extern __shared__ char smem[];
    const int tid = threadIdx.x, wid = tid >> 5, lane = tid & 31;
    const int mblk = blockIdx.x, nblk = blockIdx.y, z = blockIdx.z;

    const uint32_t sA0 = s2u(smem);
    const uint32_t sB0 = sA0 + NSTAGE * ASZ;

    const __half* Ag = g_Ax + (size_t)mblk * BM * KTP;
    const __half* Bg = (z ? g_Wv2 : g_Wq2) + (size_t)nblk * BN * KTP;

    const int ldrow = tid >> 3;
    const int ldch  = tid & 7;

    auto load_tile = [&](int buf, int k0) {
        const uint32_t a = sA0 + buf * ASZ;
        const uint32_t b = sB0 + buf * ASZ;
#pragma unroll
        for (int j = 0; j < 4; j++) {
            const int row = ldrow + j * 32;
            CP_ASYNC16(a + row * ROWB + ldch * 16,
                       Ag + (size_t)row * KTP + k0 + ldch * 8);
        }
#pragma unroll
        for (int j = 0; j < 4; j++) {
            const int row = ldrow + j * 32;
            CP_ASYNC16(b + row * ROWB + ldch * 16,
                       Bg + (size_t)row * KTP + k0 + ldch * 8);
        }
        CP_COMMIT();
    };

    float acc[2][8][4];
#pragma unroll
    for (int i = 0; i < 2; i++)
#pragma unroll
        for (int j = 0; j < 8; j++)
#pragma unroll
            for (int q = 0; q < 4; q++) acc[i][j][q] = 0.f;

    const int mbase = (wid >> 1) * 32;
    const int nbase = (wid & 1) * 64;

    const int a_row = (lane & 15);
    const int a_off = (lane >> 4) * 16;
    const int b_row = ((lane >> 4) << 3) + (lane & 7);
    const int b_off = ((lane >> 3) & 1) * 16;

    load_tile(0, 0);
    load_tile(1, BK);

#pragma unroll 1
    for (int it = 0; it < GITER; it++) {
        const int buf = it % NSTAGE;
        CP_WAIT(1);
        __syncthreads();
        if (it + 2 < GITER) load_tile((it + 2) % NSTAGE, (it + 2) * BK);

        const uint32_t sAb = sA0 + buf * ASZ;
        const uint32_t sBb = sB0 + buf * ASZ;
#pragma unroll
        for (int k16 = 0; k16 < 4; k16++) {
            uint32_t a[2][4];
#pragma unroll
            for (int i = 0; i < 2; i++) {
                const uint32_t addr = sAb
                    + (mbase + i * 16 + a_row) * ROWB + k16 * 32 + a_off;
                LDMATRIX_X4(a[i][0], a[i][1], a[i][2], a[i][3], addr);
            }
            uint32_t b[4][4];
#pragma unroll
            for (int g = 0; g < 4; g++) {
                const uint32_t addr = sBb
                    + (nbase + g * 16 + b_row) * ROWB + k16 * 32 + b_off;
                LDMATRIX_X4(b[g][0], b[g][1], b[g][2], b[g][3], addr);
            }
#pragma unroll
            for (int i = 0; i < 2; i++)
#pragma unroll
                for (int g = 0; g < 4; g++) {
                    MMA16816F(acc[i][2 * g],     a[i], (&b[g][0]));
                    MMA16816F(acc[i][2 * g + 1], a[i], (&b[g][2]));
                }
        }
    }

    const int head = nblk * 2 + (wid & 1);
    const float* nw = (z ? vw : qw) + head * HD;
    float* Out = (z ? g_V : g_Q);

    float nwv[8][2];
#pragma unroll
    for (int j = 0; j < 8; j++) {
        float2 t = *(const float2*)(nw + j * 8 + 2 * (lane & 3));
        nwv[j][0] = t.x; nwv[j][1] = t.y;
    }

#pragma unroll
    for (int i = 0; i < 2; i++) {
#pragma unroll
        for (int hh = 0; hh < 2; hh++) {
            float ss = 0.f;
#pragma unroll
            for (int j = 0; j < 8; j++) {
                const float v0 = acc[i][j][2 * hh];
                const float v1 = acc[i][j][2 * hh + 1];
                ss = fmaf(v0, v0, fmaf(v1, v1, ss));
            }
            ss += __shfl_xor_sync(0xffffffffu, ss, 1);
            ss += __shfl_xor_sync(0xffffffffu, ss, 2);
            const float inv = rsqrtf(ss * (1.0f / 64.0f) + 1e-8f);

            const int row = mblk * BM + mbase + i * 16 + hh * 8 + (lane >> 2);
            float* op = Out + (size_t)row * DD + head * HD + 2 * (lane & 3);
#pragma unroll
            for (int j = 0; j < 8; j++) {
                float2 o;
                o.x = acc[i][j][2 * hh]     * inv * nwv[j][0];
                o.y = acc[i][j][2 * hh + 1] * inv * nwv[j][1];
                *(float2*)(op + j * 8) = o;
            }
        }
    }
}

// ---------------------------------------------------------------------------
// Kernel B: per-chunk S^T[e][d] = sum_t V[t][e] * K[t][d].
// fp16 2-term: A = V^T split hi/lo, B = K^T hi only. 128 threads, 4 warps.
// ---------------------------------------------------------------------------
__global__ __launch_bounds__(128) void k_chunk_kv(const float* __restrict__ X)
{
    extern __shared__ char sm[];
    const int c = blockIdx.x, h = blockIdx.y, b = blockIdx.z;
    const int tid = threadIdx.x, wid = tid >> 5, lane = tid & 31;

    char* VThi = sm;            // 8KB each
    char* VTlo = sm + 8192;
    char* KThi = sm + 16384;

    const float* Kg = X   + ((size_t)(b * LL + c * CH)) * DD + h * HD;
    const float* Vg = g_V + ((size_t)(b * LL + c * CH)) * DD + h * HD;

    conv_tr64_h2(Vg, DD, VThi, VTlo, tid);
    conv_tr64_h1(Kg, DD, KThi, tid);
    __syncthreads();

    const uint32_t uVThi = s2u(VThi), uVTlo = s2u(VTlo);
    const uint32_t uKThi = s2u(KThi);
    const int mbase = wid * 16;
    const int arow = mbase + (lane & 15);

    float acc[8][4];
#pragma unroll
    for (int j = 0; j < 8; j++)
#pragma unroll
        for (int q = 0; q < 4; q++) acc[j][q] = 0.f;

#pragma unroll
    for (int s = 0; s < 2; s++) {
        const uint32_t Ab = s ? uVTlo : uVThi;
#pragma unroll
        for (int k16 = 0; k16 < 4; k16++) {
            uint32_t a[4];
            LDMATRIX_X4(a[0], a[1], a[2], a[3],
                Ab + arow * 128 + (((2 * k16 + (lane >> 4)) ^ (lane & 7)) << 4));
#pragma unroll
            for (int g = 0; g < 4; g++) {
                const int grow = g * 16 + ((lane >> 4) << 3) + (lane & 7);
                uint32_t bb[4];
                LDMATRIX_X4(bb[0], bb[1], bb[2], bb[3],
                    uKThi + grow * 128
                    + (((2 * k16 + ((lane >> 3) & 1)) ^ (lane & 7)) << 4));
                MMA16816F(acc[2 * g],     a, bb);
                MMA16816F(acc[2 * g + 1], a, (bb + 2));
            }
        }
    }

    float* Sp = g_S + (size_t)((b * HH + h) * NC + c) * (HD * HD);
#pragma unroll
    for (int j = 0; j < 8; j++)
#pragma unroll
        for (int hh = 0; hh < 2; hh++) {
            const int e = mbase + (lane >> 2) + 8 * hh;
            const int d = 8 * j + 2 * (lane & 3);
            float2 o = {acc[j][2 * hh], acc[j][2 * hh + 1]};
            *(float2*)(Sp + e * HD + d) = o;
        }
}

// ---------------------------------------------------------------------------
// Kernel C: EXCLUSIVE prefix sum over 16 chunks. Grid (32 bh, 16); scalar
// element per thread; all 16 loads issued before any store (MLP=16).
// ---------------------------------------------------------------------------
__global__ __launch_bounds__(256) void k_prefix()
{
    const int bh = blockIdx.x;
    const int e = blockIdx.y * 256 + threadIdx.x;
    float* base = g_S + (size_t)bh * NC * HD * HD + e;
    float v[NC];
#pragma unroll
    for (int c = 0; c < NC; c++) v[c] = base[c * (HD * HD)];
    float run = 0.f;
#pragma unroll
    for (int c = 0; c < NC; c++) {
        base[c * (HD * HD)] = run;
        run += v[c];
    }
}

// ---------------------------------------------------------------------------
// Kernel D: per-chunk output. fp16 2-term GEMMs. 128 threads, 4 warps.
//   GEMM1: [O1 | A] = Q @ [S^T-rows | K]   (causal skip in A region)
//   mask A, split fp16 hi/lo, GEMM2: O = O1 + A @ V^T
// ---------------------------------------------------------------------------
__global__ __launch_bounds__(128) void k_out(const float* __restrict__ X,
                                             float* __restrict__ Out)
{
    extern __shared__ char sm[];
    const int c = blockIdx.x, h = blockIdx.y, b = blockIdx.z;
    const int tid = threadIdx.x, wid = tid >> 5, lane = tid & 31;

    char* Qhi = sm;             // 8KB
    char* Qlo = sm + 8192;
    char* B1hi = sm + 16384;    // 16KB : rows 0-63 = S^T, rows 64-127 = K
    char* A2hi = sm + 16384;    // phase-B aliases (B1 dead after GEMM1)
    char* A2lo = sm + 24576;
    char* VThi = sm + 32768;    // 8KB

    const float* Qg = g_Q + ((size_t)(b * LL + c * CH)) * DD + h * HD;
    const float* Kg = X   + ((size_t)(b * LL + c * CH)) * DD + h * HD;
    const float* Vg = g_V + ((size_t)(b * LL + c * CH)) * DD + h * HD;
    const float* Sp = g_S + (size_t)((b * HH + h) * NC + c) * (HD * HD);

    conv_nat64_h2(Qg, DD, Qhi, Qlo, 0, tid);
    conv_nat64_h1(Sp, HD, B1hi, 0, tid);
    conv_nat64_h1(Kg, DD, B1hi, 64, tid);
    __syncthreads();

    const uint32_t uQhi = s2u(Qhi), uQlo = s2u(Qlo);
    const uint32_t uB1hi = s2u(B1hi);
    const int mbase = wid * 16;
    const int arow = mbase + (lane & 15);

    float acc[16][4];
#pragma unroll
    for (int j = 0; j < 16; j++)
#pragma unroll
        for (int q = 0; q < 4; q++) acc[j][q] = 0.f;

    // GEMM1
#pragma unroll
    for (int s = 0; s < 2; s++) {
        const uint32_t Ab = s ? uQlo : uQhi;
#pragma unroll
        for (int k16 = 0; k16 < 4; k16++) {
            uint32_t a[4];
            LDMATRIX_X4(a[0], a[1], a[2], a[3],
                Ab + arow * 128 + (((2 * k16 + (lane >> 4)) ^ (lane & 7)) << 4));
#pragma unroll
            for (int g = 0; g < 8; g++) {
                if (g >= 4 && (g - 4) > wid) continue;  // fully-masked A tiles
                const int grow = g * 16 + ((lane >> 4) << 3) + (lane & 7);
                uint32_t bb[4];
                LDMATRIX_X4(bb[0], bb[1], bb[2], bb[3],
                    uB1hi + grow * 128
                    + (((2 * k16 + ((lane >> 3) & 1)) ^ (lane & 7)) << 4));
                MMA16816F(acc[2 * g],     a, bb);
                MMA16816F(acc[2 * g + 1], a, (bb + 2));
            }
        }
    }

    __syncthreads();   // B1 reads complete; safe to overwrite with A2/VT

    // Causal mask + fp16 hi/lo split of A into smem
#pragma unroll
    for (int j = 8; j < 16; j++)
#pragma unroll
        for (int q = 0; q < 4; q++) {
            const int t = (j - 8) * 8 + 2 * (lane & 3) + (q & 1);
            const int l = mbase + (lane >> 2) + 8 * (q >> 1);
            const float v = (t <= l) ? acc[j][q] : 0.f;
            const __half hi = __float2half_rn(v);
            const __half lo = __float2half_rn(v - __half2float(hi));
            const int off = l * 128 + (((t >> 3) ^ (l & 7)) << 4) + (t & 7) * 2;
            *(__half*)(A2hi + off) = hi;
            *(__half*)(A2lo + off) = lo;
        }

    conv_tr64_h1(Vg, DD, VThi, tid);
    __syncthreads();

    const uint32_t uA2hi = s2u(A2hi), uA2lo = s2u(A2lo);
    const uint32_t uVThi = s2u(VThi);

    // GEMM2: O(acc[0..7]) += A @ V^T
#pragma unroll
    for (int s = 0; s < 2; s++) {
        const uint32_t Ab = s ? uA2lo : uA2hi;
#pragma unroll
        for (int k16 = 0; k16 < 4; k16++) {
            uint32_t a[4];
            LDMATRIX_X4(a[0], a[1], a[2], a[3],
                Ab + arow * 128 + (((2 * k16 + (lane >> 4)) ^ (lane & 7)) << 4));
#pragma unroll
            for (int g = 0; g < 4; g++) {
                const int grow = g * 16 + ((lane >> 4) << 3) + (lane & 7);
                uint32_t bb[4];
                LDMATRIX_X4(bb[0], bb[1], bb[2], bb[3],
                    uVThi + grow * 128
                    + (((2 * k16 + ((lane >> 3) & 1)) ^ (lane & 7)) << 4));
                MMA16816F(acc[2 * g],     a, bb);
                MMA16816F(acc[2 * g + 1], a, (bb + 2));
            }
        }
    }

    // Write O
    float* Op = Out + ((size_t)(b * LL + c * CH)) * DD + h * HD;
#pragma unroll
    for (int j = 0; j < 8; j++)
#pragma unroll
        for (int hh = 0; hh < 2; hh++) {
            const int l = mbase + (lane >> 2) + 8 * hh;
            const int e = 8 * j + 2 * (lane & 3);
            float2 o = {acc[j][2 * hh], acc[j][2 * hh + 1]};
            *(float2*)(Op + (size_t)l * DD + e) = o;
        }
}

// ---------------------------------------------------------------------------
extern "C" void kernel_launch(void* const* d_in, const int* in_sizes, int n_in,
                              void* d_out, int out_size)
{
    const float* X  = (const float*)d_in[0];
    const float* Wq = (const float*)d_in[1];
    const float* Wv = (const float*)d_in[2];
    const float* qw = (const float*)d_in[3];
    const float* vw = (const float*)d_in[4];
    float* Out = (float*)d_out;

    const int SMEM_PROJ = 2 * NSTAGE * ASZ;  // 110592 bytes
    cudaFuncSetAttribute(k_proj, cudaFuncAttributeMaxDynamicSharedMemorySize,
                         SMEM_PROJ);
    cudaFuncSetAttribute(k_out, cudaFuncAttributeMaxDynamicSharedMemorySize,
                         40960);
    cudaFuncSetAttribute(k_chunk_kv,
                         cudaFuncAttributeMaxDynamicSharedMemorySize, 24576);

    k_split   <<<dim3(1024, 1, 3), 256>>>(X, Wq, Wv);
    k_proj    <<<dim3(16, 8, 2), 256, SMEM_PROJ>>>(qw, vw);
    k_chunk_kv<<<dim3(16, 16, 2), 128, 24576>>>(X);
    k_prefix  <<<dim3(32, 16), 256>>>();
    k_out     <<<dim3(16, 16, 2), 128, 40960>>>(X, Out);
}

// round 14
// speedup vs baseline: 4.8098x; 1.0165x over previous
#include <cuda_runtime.h>
#include <cuda_bf16.h>
#include <cuda_fp16.h>
#include <cstdint>
#include <cstring>

// Problem constants (fixed shapes from reference)
#define BB   2
#define LL   1024
#define DD   1024
#define HH   16
#define HD   64      // head dim
#define NC   16      // number of chunks per sequence
#define CH   64      // chunk length
#define MTOT (BB*LL) // 2048 rows

// Projection GEMM: plain fp16, K = 1024.  CTA 128x256, warp 64x64.
#define KTP  1024
#define BK   64
#define GITER (KTP/BK)    // 16
#define BM   128
#define BN   256
#define ROWB 144          // padded smem row stride in bytes (64 x 2B + 16 pad)
#define ASZB (128*ROWB)   // A stage: 18432 bytes
#define BSZB (256*ROWB)   // B stage: 36864 bytes
#define STGB (ASZB+BSZB)  // 55296 per stage
#define NSTAGE 3

// Scratch (no allocations allowed in kernel_launch)
__device__ float g_Q[MTOT * DD];                 // 8 MB : normalized Q
__device__ float g_V[MTOT * DD];                 // 8 MB : normalized V
__device__ float g_S[BB * HH * NC * HD * HD];    // 8 MB : per-chunk S^T sums
__device__ __half g_Ax [MTOT * KTP];             // 4 MB : X (fp16)
__device__ __half g_Wq2[DD * KTP];               // 2 MB : Wq (fp16)
__device__ __half g_Wv2[DD * KTP];               // 2 MB : Wv (fp16)

static __device__ __forceinline__ uint32_t s2u(const void* p) {
    uint32_t a;
    asm("{ .reg .u64 t; cvta.to.shared.u64 t, %1; cvt.u32.u64 %0, t; }"
        : "=r"(a) : "l"(p));
    return a;
}
static __device__ __forceinline__ uint32_t h2u(__half2 v) {
    uint32_t u; memcpy(&u, &v, 4); return u;
}

#define CP_ASYNC16(saddr, gptr) \
    asm volatile("cp.async.cg.shared.global [%0], [%1], 16;" \
                 :: "r"(saddr), "l"(gptr))
#define CP_COMMIT() asm volatile("cp.async.commit_group;")
#define CP_WAIT(n)  asm volatile("cp.async.wait_group %0;" :: "n"(n))

#define LDMATRIX_X4(r0, r1, r2, r3, addr) \
    asm volatile("ldmatrix.sync.aligned.m8n8.x4.shared.b16 {%0,%1,%2,%3}, [%4];" \
                 : "=r"(r0), "=r"(r1), "=r"(r2), "=r"(r3) : "r"(addr))

// fp16 MMA (all kernels)
#define MMA16816F(d, a, b) \
    asm volatile("mma.sync.aligned.m16n8k16.row.col.f32.f16.f16.f32 " \
                 "{%0,%1,%2,%3}, {%4,%5,%6,%7}, {%8,%9}, {%0,%1,%2,%3};" \
                 : "+f"((d)[0]), "+f"((d)[1]), "+f"((d)[2]), "+f"((d)[3]) \
                 : "r"((a)[0]), "r"((a)[1]), "r"((a)[2]), "r"((a)[3]),   \
                   "r"((b)[0]), "r"((b)[1]))

// ---------------------------------------------------------------------------
// fp32 64x64 -> fp16 into XOR-swizzled smem (128B rows, chunk^(row&7)).
// _h2: hi + lo (A operands, exact to 2^-22);  _h1: hi only (B operands).
// ---------------------------------------------------------------------------
static __device__ __forceinline__ void conv_nat64_h2(
    const float* __restrict__ src, int stride, char* dhi, char* dlo,
    int rowoff, int tid)
{
#pragma unroll
    for (int p = 0; p < 8; p++) {
        const int f = tid + p * 128;
        const int r = f >> 4, cc = (f & 15) * 4;
        float4 v = *(const float4*)(src + (size_t)r * stride + cc);
        float vs[4] = {v.x, v.y, v.z, v.w};
        __half h[4], l[4];
#pragma unroll
        for (int i = 0; i < 4; i++) {
            h[i] = __float2half_rn(vs[i]);
            l[i] = __float2half_rn(vs[i] - __half2float(h[i]));
        }
        uint2 H = { h2u(__halves2half2(h[0], h[1])),
                    h2u(__halves2half2(h[2], h[3])) };
        uint2 L = { h2u(__halves2half2(l[0], l[1])),
                    h2u(__halves2half2(l[2], l[3])) };
        const int row = r + rowoff;
        const int off = row * 128 + (((cc >> 3) ^ (row & 7)) << 4) + (cc & 7) * 2;
        *(uint2*)(dhi + off) = H;
        *(uint2*)(dlo + off) = L;
    }
}

static __device__ __forceinline__ void conv_nat64_h1(
    const float* __restrict__ src, int stride, char* dhi, int rowoff, int tid)
{
#pragma unroll
    for (int p = 0; p < 8; p++) {
        const int f = tid + p * 128;
        const int r = f >> 4, cc = (f & 15) * 4;
        float4 v = *(const float4*)(src + (size_t)r * stride + cc);
        uint2 H = { h2u(__halves2half2(__float2half_rn(v.x),
                                       __float2half_rn(v.y))),
                    h2u(__halves2half2(__float2half_rn(v.z),
                                       __float2half_rn(v.w))) };
        const int row = r + rowoff;
        const int off = row * 128 + (((cc >> 3) ^ (row & 7)) << 4) + (cc & 7) * 2;
        *(uint2*)(dhi + off) = H;
    }
}

// transposed variants: dst row = src col, dst col = src row.
static __device__ __forceinline__ void conv_tr64_h2(
    const float* __restrict__ src, int stride, char* dhi, char* dlo, int tid)
{
#pragma unroll
    for (int p = 0; p < 8; p++) {
        const int f = tid + p * 128;
        const int r = f >> 4, cc = (f & 15) * 4;
        float4 v = *(const float4*)(src + (size_t)r * stride + cc);
        float vs[4] = {v.x, v.y, v.z, v.w};
#pragma unroll
        for (int i = 0; i < 4; i++) {
            __half hi = __float2half_rn(vs[i]);
            __half lo = __float2half_rn(vs[i] - __half2float(hi));
            const int row = cc + i, col = r;
            const int off = row * 128 + (((col >> 3) ^ (row & 7)) << 4)
                          + (col & 7) * 2;
            *(__half*)(dhi + off) = hi;
            *(__half*)(dlo + off) = lo;
        }
    }
}

static __device__ __forceinline__ void conv_tr64_h1(
    const float* __restrict__ src, int stride, char* dhi, int tid)
{
#pragma unroll
    for (int p = 0; p < 8; p++) {
        const int f = tid + p * 128;
        const int r = f >> 4, cc = (f & 15) * 4;
        float4 v = *(const float4*)(src + (size_t)r * stride + cc);
        float vs[4] = {v.x, v.y, v.z, v.w};
#pragma unroll
        for (int i = 0; i < 4; i++) {
            const int row = cc + i, col = r;
            const int off = row * 128 + (((col >> 3) ^ (row & 7)) << 4)
                          + (col & 7) * 2;
            *(__half*)(dhi + off) = __float2half_rn(vs[i]);
        }
    }
}

// ---------------------------------------------------------------------------
// Kernel S: fp32 -> fp16.  8 elements/thread, one 16B store.
// ---------------------------------------------------------------------------
__global__ __launch_bounds__(256) void k_split(
    const float* __restrict__ X, const float* __restrict__ Wq,
    const float* __restrict__ Wv)
{
    const int z = blockIdx.z;
    const float* src = (z == 0) ? X : (z == 1) ? Wq : Wv;
    __half* dst = (z == 0) ? g_Ax : (z == 1) ? g_Wq2 : g_Wv2;
    const int rows = (z == 0) ? MTOT : DD;

    const int gid = blockIdx.x * 256 + threadIdx.x;
    const int idx8 = gid * 8;
    if (idx8 >= rows * DD) return;

    const float* sp = src + (size_t)idx8;
    float4 v0 = *(const float4*)(sp);
    float4 v1 = *(const float4*)(sp + 4);
    float vs[8] = {v0.x, v0.y, v0.z, v0.w, v1.x, v1.y, v1.z, v1.w};
    __half h[8];
#pragma unroll
    for (int i = 0; i < 8; i++) h[i] = __float2half_rn(vs[i]);
    uint4 HU;
    HU.x = h2u(__halves2half2(h[0], h[1]));
    HU.y = h2u(__halves2half2(h[2], h[3]));
    HU.z = h2u(__halves2half2(h[4], h[5]));
    HU.w = h2u(__halves2half2(h[6], h[7]));
    *(uint4*)(dst + (size_t)idx8) = HU;
}

// ---------------------------------------------------------------------------
// Kernel P: projection GEMM via fp16 mma.sync + fused per-head RMSNorm.
// CTA 128x256, warp 64x64 (2m x 4n warps), K=1024, 3-stage cp.async.
// Grid (16 m, 4 n, 2 {Q,V}) = 128 CTAs, 1 CTA/SM.
// ---------------------------------------------------------------------------
__global__ __launch_bounds__(256, 1) void k_proj(
    const float* __restrict__ qw, const float* __restrict__ vw)
{
    extern __shared__ char smem[];
    const int tid = threadIdx.x, wid = tid >> 5, lane = tid & 31;
    const int mblk = blockIdx.x, nblk = blockIdx.y, z = blockIdx.z;

    const uint32_t sBase = s2u(smem);

    const __half* Ag = g_Ax + (size_t)mblk * BM * KTP;
    const __half* Bg = (z ? g_Wv2 : g_Wq2) + (size_t)nblk * BN * KTP;

    auto load_tile = [&](int buf, int k0) {
        const uint32_t a = sBase + buf * STGB;
        const uint32_t b = a + ASZB;
#pragma unroll
        for (int j = 0; j < 4; j++) {               // A: 1024 16B chunks
            const int u = tid + j * 256;
            const int row = u >> 3, ch = u & 7;
            CP_ASYNC16(a + row * ROWB + ch * 16,
                       Ag + (size_t)row * KTP + k0 + ch * 8);
        }
#pragma unroll
        for (int j = 0; j < 8; j++) {               // B: 2048 16B chunks
            const int u = tid + j * 256;
            const int row = u >> 3, ch = u & 7;
            CP_ASYNC16(b + row * ROWB + ch * 16,
                       Bg + (size_t)row * KTP + k0 + ch * 8);
        }
        CP_COMMIT();
    };

    float acc[4][8][4];
#pragma unroll
    for (int i = 0; i < 4; i++)
#pragma unroll
        for (int j = 0; j < 8; j++)
#pragma unroll
            for (int q = 0; q < 4; q++) acc[i][j][q] = 0.f;

    const int mbase = (wid >> 2) * 64;      // warp m-offset within 128
    const int nbase = (wid & 3) * 64;       // warp n-offset within 256

    const int a_row = (lane & 15);
    const int a_off = (lane >> 4) * 16;
    const int b_row = ((lane >> 4) << 3) + (lane & 7);
    const int b_off = ((lane >> 3) & 1) * 16;

    load_tile(0, 0);
    load_tile(1, BK);

#pragma unroll 1
    for (int it = 0; it < GITER; it++) {
        const int buf = it % NSTAGE;
        CP_WAIT(1);
        __syncthreads();
        if (it + 2 < GITER) load_tile((it + 2) % NSTAGE, (it + 2) * BK);

        const uint32_t sAb = sBase + buf * STGB;
        const uint32_t sBb = sAb + ASZB;
#pragma unroll
        for (int k16 = 0; k16 < 4; k16++) {
            uint32_t a[4][4];
#pragma unroll
            for (int i = 0; i < 4; i++) {
                const uint32_t addr = sAb
                    + (mbase + i * 16 + a_row) * ROWB + k16 * 32 + a_off;
                LDMATRIX_X4(a[i][0], a[i][1], a[i][2], a[i][3], addr);
            }
#pragma unroll
            for (int g = 0; g < 4; g++) {
                uint32_t b[4];
                const uint32_t addr = sBb
                    + (nbase + g * 16 + b_row) * ROWB + k16 * 32 + b_off;
                LDMATRIX_X4(b[0], b[1], b[2], b[3], addr);
#pragma unroll
                for (int i = 0; i < 4; i++) {
                    MMA16816F(acc[i][2 * g],     a[i], (&b[0]));
                    MMA16816F(acc[i][2 * g + 1], a[i], (&b[2]));
                }
            }
        }
    }

    // Epilogue: per-head RMSNorm; warp owns a full 64-wide head, 64 rows.
    const int head = nblk * 4 + (wid & 3);
    const float* nw = (z ? vw : qw) + head * HD;
    float* Out = (z ? g_V : g_Q);

    float nwv[8][2];
#pragma unroll
    for (int j = 0; j < 8; j++) {
        float2 t = *(const float2*)(nw + j * 8 + 2 * (lane & 3));
        nwv[j][0] = t.x; nwv[j][1] = t.y;
    }

#pragma unroll
    for (int i = 0; i < 4; i++) {
#pragma unroll
        for (int hh = 0; hh < 2; hh++) {   // row halves: c0/c1 vs c2/c3
            float ss = 0.f;
#pragma unroll
            for (int j = 0; j < 8; j++) {
                const float v0 = acc[i][j][2 * hh];
                const float v1 = acc[i][j][2 * hh + 1];
                ss = fmaf(v0, v0, fmaf(v1, v1, ss));
            }
            ss += __shfl_xor_sync(0xffffffffu, ss, 1);
            ss += __shfl_xor_sync(0xffffffffu, ss, 2);
            const float inv = rsqrtf(ss * (1.0f / 64.0f) + 1e-8f);

            const int row = mblk * BM + mbase + i * 16 + hh * 8 + (lane >> 2);
            float* op = Out + (size_t)row * DD + head * HD + 2 * (lane & 3);
#pragma unroll
            for (int j = 0; j < 8; j++) {
                float2 o;
                o.x = acc[i][j][2 * hh]     * inv * nwv[j][0];
                o.y = acc[i][j][2 * hh + 1] * inv * nwv[j][1];
                *(float2*)(op + j * 8) = o;
            }
        }
    }
}

// ---------------------------------------------------------------------------
// Kernel B: per-chunk S^T[e][d] = sum_t V[t][e] * K[t][d].
// fp16 2-term: A = V^T split hi/lo, B = K^T hi only. 128 threads, 4 warps.
// ---------------------------------------------------------------------------
__global__ __launch_bounds__(128) void k_chunk_kv(const float* __restrict__ X)
{
    extern __shared__ char sm[];
    const int c = blockIdx.x, h = blockIdx.y, b = blockIdx.z;
    const int tid = threadIdx.x, wid = tid >> 5, lane = tid & 31;

    char* VThi = sm;            // 8KB each
    char* VTlo = sm + 8192;
    char* KThi = sm + 16384;

    const float* Kg = X   + ((size_t)(b * LL + c * CH)) * DD + h * HD;
    const float* Vg = g_V + ((size_t)(b * LL + c * CH)) * DD + h * HD;

    conv_tr64_h2(Vg, DD, VThi, VTlo, tid);
    conv_tr64_h1(Kg, DD, KThi, tid);
    __syncthreads();

    const uint32_t uVThi = s2u(VThi), uVTlo = s2u(VTlo);
    const uint32_t uKThi = s2u(KThi);
    const int mbase = wid * 16;
    const int arow = mbase + (lane & 15);

    float acc[8][4];
#pragma unroll
    for (int j = 0; j < 8; j++)
#pragma unroll
        for (int q = 0; q < 4; q++) acc[j][q] = 0.f;

#pragma unroll
    for (int s = 0; s < 2; s++) {
        const uint32_t Ab = s ? uVTlo : uVThi;
#pragma unroll
        for (int k16 = 0; k16 < 4; k16++) {
            uint32_t a[4];
            LDMATRIX_X4(a[0], a[1], a[2], a[3],
                Ab + arow * 128 + (((2 * k16 + (lane >> 4)) ^ (lane & 7)) << 4));
#pragma unroll
            for (int g = 0; g < 4; g++) {
                const int grow = g * 16 + ((lane >> 4) << 3) + (lane & 7);
                uint32_t bb[4];
                LDMATRIX_X4(bb[0], bb[1], bb[2], bb[3],
                    uKThi + grow * 128
                    + (((2 * k16 + ((lane >> 3) & 1)) ^ (lane & 7)) << 4));
                MMA16816F(acc[2 * g],     a, bb);
                MMA16816F(acc[2 * g + 1], a, (bb + 2));
            }
        }
    }

    float* Sp = g_S + (size_t)((b * HH + h) * NC + c) * (HD * HD);
#pragma unroll
    for (int j = 0; j < 8; j++)
#pragma unroll
        for (int hh = 0; hh < 2; hh++) {
            const int e = mbase + (lane >> 2) + 8 * hh;
            const int d = 8 * j + 2 * (lane & 3);
            float2 o = {acc[j][2 * hh], acc[j][2 * hh + 1]};
            *(float2*)(Sp + e * HD + d) = o;
        }
}

// ---------------------------------------------------------------------------
// Kernel C: EXCLUSIVE prefix sum over 16 chunks. Grid (32 bh, 16); scalar
// element per thread; all 16 loads issued before any store (MLP=16).
// ---------------------------------------------------------------------------
__global__ __launch_bounds__(256) void k_prefix()
{
    const int bh = blockIdx.x;
    const int e = blockIdx.y * 256 + threadIdx.x;
    float* base = g_S + (size_t)bh * NC * HD * HD + e;
    float v[NC];
#pragma unroll
    for (int c = 0; c < NC; c++) v[c] = base[c * (HD * HD)];
    float run = 0.f;
#pragma unroll
    for (int c = 0; c < NC; c++) {
        base[c * (HD * HD)] = run;
        run += v[c];
    }
}

// ---------------------------------------------------------------------------
// Kernel D: per-chunk output. fp16 2-term GEMMs. 128 threads, 4 warps.
//   GEMM1: [O1 | A] = Q @ [S^T-rows | K]   (causal skip in A region)
//   mask A, split fp16 hi/lo, GEMM2: O = O1 + A @ V^T
// ---------------------------------------------------------------------------
__global__ __launch_bounds__(128) void k_out(const float* __restrict__ X,
                                             float* __restrict__ Out)
{
    extern __shared__ char sm[];
    const int c = blockIdx.x, h = blockIdx.y, b = blockIdx.z;
    const int tid = threadIdx.x, wid = tid >> 5, lane = tid & 31;

    char* Qhi = sm;             // 8KB
    char* Qlo = sm + 8192;
    char* B1hi = sm + 16384;    // 16KB : rows 0-63 = S^T, rows 64-127 = K
    char* A2hi = sm + 16384;    // phase-B aliases (B1 dead after GEMM1)
    char* A2lo = sm + 24576;
    char* VThi = sm + 32768;    // 8KB

    const float* Qg = g_Q + ((size_t)(b * LL + c * CH)) * DD + h * HD;
    const float* Kg = X   + ((size_t)(b * LL + c * CH)) * DD + h * HD;
    const float* Vg = g_V + ((size_t)(b * LL + c * CH)) * DD + h * HD;
    const float* Sp = g_S + (size_t)((b * HH + h) * NC + c) * (HD * HD);

    conv_nat64_h2(Qg, DD, Qhi, Qlo, 0, tid);
    conv_nat64_h1(Sp, HD, B1hi, 0, tid);
    conv_nat64_h1(Kg, DD, B1hi, 64, tid);
    __syncthreads();

    const uint32_t uQhi = s2u(Qhi), uQlo = s2u(Qlo);
    const uint32_t uB1hi = s2u(B1hi);
    const int mbase = wid * 16;
    const int arow = mbase + (lane & 15);

    float acc[16][4];
#pragma unroll
    for (int j = 0; j < 16; j++)
#pragma unroll
        for (int q = 0; q < 4; q++) acc[j][q] = 0.f;

    // GEMM1
#pragma unroll
    for (int s = 0; s < 2; s++) {
        const uint32_t Ab = s ? uQlo : uQhi;
#pragma unroll
        for (int k16 = 0; k16 < 4; k16++) {
            uint32_t a[4];
            LDMATRIX_X4(a[0], a[1], a[2], a[3],
                Ab + arow * 128 + (((2 * k16 + (lane >> 4)) ^ (lane & 7)) << 4));
#pragma unroll
            for (int g = 0; g < 8; g++) {
                if (g >= 4 && (g - 4) > wid) continue;  // fully-masked A tiles
                const int grow = g * 16 + ((lane >> 4) << 3) + (lane & 7);
                uint32_t bb[4];
                LDMATRIX_X4(bb[0], bb[1], bb[2], bb[3],
                    uB1hi + grow * 128
                    + (((2 * k16 + ((lane >> 3) & 1)) ^ (lane & 7)) << 4));
                MMA16816F(acc[2 * g],     a, bb);
                MMA16816F(acc[2 * g + 1], a, (bb + 2));
            }
        }
    }

    __syncthreads();   // B1 reads complete; safe to overwrite with A2/VT

    // Causal mask + fp16 hi/lo split of A into smem
#pragma unroll
    for (int j = 8; j < 16; j++)
#pragma unroll
        for (int q = 0; q < 4; q++) {
            const int t = (j - 8) * 8 + 2 * (lane & 3) + (q & 1);
            const int l = mbase + (lane >> 2) + 8 * (q >> 1);
            const float v = (t <= l) ? acc[j][q] : 0.f;
            const __half hi = __float2half_rn(v);
            const __half lo = __float2half_rn(v - __half2float(hi));
            const int off = l * 128 + (((t >> 3) ^ (l & 7)) << 4) + (t & 7) * 2;
            *(__half*)(A2hi + off) = hi;
            *(__half*)(A2lo + off) = lo;
        }

    conv_tr64_h1(Vg, DD, VThi, tid);
    __syncthreads();

    const uint32_t uA2hi = s2u(A2hi), uA2lo = s2u(A2lo);
    const uint32_t uVThi = s2u(VThi);

    // GEMM2: O(acc[0..7]) += A @ V^T
#pragma unroll
    for (int s = 0; s < 2; s++) {
        const uint32_t Ab = s ? uA2lo : uA2hi;
#pragma unroll
        for (int k16 = 0; k16 < 4; k16++) {
            uint32_t a[4];
            LDMATRIX_X4(a[0], a[1], a[2], a[3],
                Ab + arow * 128 + (((2 * k16 + (lane >> 4)) ^ (lane & 7)) << 4));
#pragma unroll
            for (int g = 0; g < 4; g++) {
                const int grow = g * 16 + ((lane >> 4) << 3) + (lane & 7);
                uint32_t bb[4];
                LDMATRIX_X4(bb[0], bb[1], bb[2], bb[3],
                    uVThi + grow * 128
                    + (((2 * k16 + ((lane >> 3) & 1)) ^ (lane & 7)) << 4));
                MMA16816F(acc[2 * g],     a, bb);
                MMA16816F(acc[2 * g + 1], a, (bb + 2));
            }
        }
    }

    // Write O
    float* Op = Out + ((size_t)(b * LL + c * CH)) * DD + h * HD;
#pragma unroll
    for (int j = 0; j < 8; j++)
#pragma unroll
        for (int hh = 0; hh < 2; hh++) {
            const int l = mbase + (lane >> 2) + 8 * hh;
            const int e = 8 * j + 2 * (lane & 3);
            float2 o = {acc[j][2 * hh], acc[j][2 * hh + 1]};
            *(float2*)(Op + (size_t)l * DD + e) = o;
        }
}

// ---------------------------------------------------------------------------
extern "C" void kernel_launch(void* const* d_in, const int* in_sizes, int n_in,
                              void* d_out, int out_size)
{
    const float* X  = (const float*)d_in[0];
    const float* Wq = (const float*)d_in[1];
    const float* Wv = (const float*)d_in[2];
    const float* qw = (const float*)d_in[3];
    const float* vw = (const float*)d_in[4];
    float* Out = (float*)d_out;

    const int SMEM_PROJ = NSTAGE * STGB;  // 165888 bytes
    cudaFuncSetAttribute(k_proj, cudaFuncAttributeMaxDynamicSharedMemorySize,
                         SMEM_PROJ);
    cudaFuncSetAttribute(k_out, cudaFuncAttributeMaxDynamicSharedMemorySize,
                         40960);
    cudaFuncSetAttribute(k_chunk_kv,
                         cudaFuncAttributeMaxDynamicSharedMemorySize, 24576);

    k_split   <<<dim3(1024, 1, 3), 256>>>(X, Wq, Wv);
    k_proj    <<<dim3(16, 4, 2), 256, SMEM_PROJ>>>(qw, vw);
    k_chunk_kv<<<dim3(16, 16, 2), 128, 24576>>>(X);
    k_prefix  <<<dim3(32, 16), 256>>>();
    k_out     <<<dim3(16, 16, 2), 128, 40960>>>(X, Out);
}